// round 7
// baseline (speedup 1.0000x reference)
#include <cuda_runtime.h>
#include <cuda_bf16.h>
#include <cstdint>
#include <math.h>

// ============================================================================
// EnsembleRatioModel — round 6: identical to round 5 (infra failure, resubmit).
// bf16-split (3xBF16 ~ fp32) mma.sync GEMM chain with ldmatrix fragment loads.
//
// Output packing (validated): [N*512) repr_ ; [3N) r*m ; [3N) s*m ; [3N) m
// ============================================================================

#define GN 131072

__device__ unsigned short g_hiA[GN * 512];
__device__ unsigned short g_loA[GN * 512];
__device__ unsigned short g_hiB[GN * 512];
__device__ unsigned short g_loB[GN * 512];
__device__ unsigned short g_hiC[GN * 256];
__device__ unsigned short g_loC[GN * 256];
__device__ unsigned short g_hiX[GN * 64];
__device__ unsigned short g_loX[GN * 64];
__device__ unsigned short g_whi[1736704];
__device__ unsigned short g_wlo[1736704];

#define OFF_W0   0u
#define OFF_W1   32768u
#define OFF_W2   294912u
#define OFF_SW0  557056u      /* + p*262144 */
#define OFF_SW1  1343488u     /* + p*131072 */

// ---------------- helpers ----------------------------------------------------
__device__ __forceinline__ uint32_t smem_u32(const void* p) {
    uint32_t a;
    asm("{ .reg .u64 t; cvta.to.shared.u64 t, %1; cvt.u32.u64 %0, t; }"
        : "=r"(a) : "l"(p));
    return a;
}
__device__ __forceinline__ void cpasync16(uint32_t dst, const void* src) {
    asm volatile("cp.async.cg.shared.global [%0], [%1], 16;"
                 :: "r"(dst), "l"(src) : "memory");
}
__device__ __forceinline__ void ldsm_x4(uint32_t* r, uint32_t addr) {
    asm volatile("ldmatrix.sync.aligned.m8n8.x4.shared.b16 {%0,%1,%2,%3}, [%4];"
                 : "=r"(r[0]), "=r"(r[1]), "=r"(r[2]), "=r"(r[3]) : "r"(addr));
}
__device__ __forceinline__ void mma_bf16(float* d, const uint32_t* a,
                                         const uint32_t* b) {
    asm volatile(
        "mma.sync.aligned.m16n8k16.row.col.f32.bf16.bf16.f32 "
        "{%0,%1,%2,%3}, {%4,%5,%6,%7}, {%8,%9}, {%0,%1,%2,%3};"
        : "+f"(d[0]), "+f"(d[1]), "+f"(d[2]), "+f"(d[3])
        : "r"(a[0]), "r"(a[1]), "r"(a[2]), "r"(a[3]), "r"(b[0]), "r"(b[1]));
}
__device__ __forceinline__ void split_bf16(float v, __nv_bfloat16& h, __nv_bfloat16& l) {
    h = __float2bfloat16(v);
    l = __float2bfloat16(v - __bfloat162float(h));
}

// ============================================================================
// GEMM: C[M,Ntot] = (Ahi+Alo)[M,K] @ (Whi+Wlo)^T   (W stored [Ntot,K])
// 128x128 CTA tile, 256 threads, warp tile 64x32, K-chunk 32, double buffer.
// SMEM per stage: 4 components x 128 rows x 40 bf16 (pitch 80B) = 40960 B.
// ============================================================================
#define STAGE_BYTES 40960
#define COMP_BYTES  10240
#define ROW_PITCH   80

__global__ void __launch_bounds__(256)
gemm_mma(const __nv_bfloat16* __restrict__ Ahi, const __nv_bfloat16* __restrict__ Alo,
         const __nv_bfloat16* __restrict__ Whi, const __nv_bfloat16* __restrict__ Wlo,
         const float* __restrict__ bias,
         float* __restrict__ raw_out,
         __nv_bfloat16* __restrict__ Ohi, __nv_bfloat16* __restrict__ Olo,
         int K, int Ntot, int write_raw)
{
    extern __shared__ __align__(16) char smem[];
    const uint32_t smem_base = smem_u32(smem);

    const int tid   = threadIdx.x;
    const int wid   = tid >> 5;
    const int lane  = tid & 31;
    const int g     = lane >> 2;
    const int tk    = lane & 3;
    const int warpM = wid >> 2;       // 0..1 -> 64-row half
    const int warpN = wid & 3;        // 0..3 -> 32-col quarter
    const int m0 = blockIdx.y * 128;
    const int n0 = blockIdx.x * 128;

    const int nk = K >> 5;

    // ldmatrix lane-address components (within a 16x16 A tile / 16(n)x16(k) B pair)
    const uint32_t a_lrow = (uint32_t)(lane & 15) * ROW_PITCH + (uint32_t)(lane >> 4) * 16;
    const uint32_t b_lrow = (uint32_t)((lane & 7) + ((lane >> 4) << 3)) * ROW_PITCH
                          + (uint32_t)((lane >> 3) & 1) * 16;

    auto load_chunk = [&](int c, int s) {
        const uint32_t st = smem_base + (uint32_t)s * STAGE_BYTES;
        const int koff = c * 32;
#pragma unroll
        for (int i = 0; i < 8; i++) {
            int idx  = i * 256 + tid;
            int comp = idx >> 9;
            int rem  = idx & 511;
            int row  = rem >> 2;
            int seg  = rem & 3;
            uint32_t dst = st + (uint32_t)comp * COMP_BYTES
                         + (uint32_t)row * ROW_PITCH + (uint32_t)seg * 16;
            const __nv_bfloat16* src;
            size_t roff;
            if (comp == 0)      { src = Ahi; roff = (size_t)(m0 + row) * K; }
            else if (comp == 1) { src = Alo; roff = (size_t)(m0 + row) * K; }
            else if (comp == 2) { src = Whi; roff = (size_t)(n0 + row) * K; }
            else                { src = Wlo; roff = (size_t)(n0 + row) * K; }
            cpasync16(dst, src + roff + koff + seg * 8);
        }
        asm volatile("cp.async.commit_group;" ::: "memory");
    };

    float acc[4][4][4];
#pragma unroll
    for (int i = 0; i < 4; i++)
#pragma unroll
        for (int j = 0; j < 4; j++)
#pragma unroll
            for (int r = 0; r < 4; r++) acc[i][j][r] = 0.f;

    load_chunk(0, 0);

    for (int c = 0; c < nk; c++) {
        if (c + 1 < nk) {
            load_chunk(c + 1, (c + 1) & 1);
            asm volatile("cp.async.wait_group 1;" ::: "memory");
        } else {
            asm volatile("cp.async.wait_group 0;" ::: "memory");
        }
        __syncthreads();

        const uint32_t sb = smem_base + (uint32_t)(c & 1) * STAGE_BYTES;
        const uint32_t aBase = sb + (uint32_t)(warpM * 64) * ROW_PITCH;
        const uint32_t bBase = sb + 2u * COMP_BYTES + (uint32_t)(warpN * 32) * ROW_PITCH;

#pragma unroll
        for (int t = 0; t < 2; t++) {
            const uint32_t kb = (uint32_t)t * 32;

            // B fragments: 2 x ldsm_x4 hi, 2 x lo (each covers two n8 tiles)
            uint32_t bh[4][2], bl[4][2];
#pragma unroll
            for (int jj = 0; jj < 2; jj++) {
                uint32_t r4[4];
                uint32_t addr = bBase + (uint32_t)(jj * 16) * ROW_PITCH + kb + b_lrow;
                ldsm_x4(r4, addr);
                bh[jj * 2][0] = r4[0]; bh[jj * 2][1] = r4[1];
                bh[jj * 2 + 1][0] = r4[2]; bh[jj * 2 + 1][1] = r4[3];
                ldsm_x4(r4, addr + COMP_BYTES);
                bl[jj * 2][0] = r4[0]; bl[jj * 2][1] = r4[1];
                bl[jj * 2 + 1][0] = r4[2]; bl[jj * 2 + 1][1] = r4[3];
            }
            // A hi fragments: 4 x ldsm_x4
            uint32_t ah[4][4];
#pragma unroll
            for (int i = 0; i < 4; i++)
                ldsm_x4(ah[i], aBase + (uint32_t)(i * 16) * ROW_PITCH + kb + a_lrow);

#pragma unroll
            for (int i = 0; i < 4; i++)
#pragma unroll
                for (int j = 0; j < 4; j++) {
                    mma_bf16(acc[i][j], ah[i], bh[j]);
                    mma_bf16(acc[i][j], ah[i], bl[j]);
                }
            // A lo fragments
            uint32_t al[4][4];
#pragma unroll
            for (int i = 0; i < 4; i++)
                ldsm_x4(al[i], aBase + COMP_BYTES + (uint32_t)(i * 16) * ROW_PITCH + kb + a_lrow);
#pragma unroll
            for (int i = 0; i < 4; i++)
#pragma unroll
                for (int j = 0; j < 4; j++)
                    mma_bf16(acc[i][j], al[i], bh[j]);
        }
        __syncthreads();
    }

    // ---- epilogue -----------------------------------------------------------
#pragma unroll
    for (int j = 0; j < 4; j++) {
        const int cc = n0 + warpN * 32 + j * 8 + tk * 2;
        const float b0v = bias[cc];
        const float b1v = bias[cc + 1];
#pragma unroll
        for (int i = 0; i < 4; i++) {
            const int r0 = m0 + warpM * 64 + i * 16 + g;
#pragma unroll
            for (int half = 0; half < 2; half++) {
                const int r = r0 + half * 8;
                float v0 = acc[i][j][half * 2 + 0] + b0v;
                float v1 = acc[i][j][half * 2 + 1] + b1v;
                const size_t off = (size_t)r * Ntot + cc;
                if (write_raw)
                    *(float2*)(raw_out + off) = make_float2(v0, v1);
                v0 = fmaxf(v0, 0.f);
                v1 = fmaxf(v1, 0.f);
                __nv_bfloat16 h0, l0, h1, l1;
                split_bf16(v0, h0, l0);
                split_bf16(v1, h1, l1);
                uint32_t hp = (uint32_t)__bfloat16_as_ushort(h0)
                            | ((uint32_t)__bfloat16_as_ushort(h1) << 16);
                uint32_t lp = (uint32_t)__bfloat16_as_ushort(l0)
                            | ((uint32_t)__bfloat16_as_ushort(l1) << 16);
                *(uint32_t*)(Ohi + off) = hp;
                *(uint32_t*)(Olo + off) = lp;
            }
        }
    }
}

// ---- prep: relu + bf16 hi/lo split of x -------------------------------------
__global__ void prep_split_relu(const float* __restrict__ src,
                                __nv_bfloat16* __restrict__ hi,
                                __nv_bfloat16* __restrict__ lo, int n)
{
    int t = blockIdx.x * blockDim.x + threadIdx.x;
    if (t >= n) return;
    float v = fmaxf(src[t], 0.0f);
    __nv_bfloat16 h, l;
    split_bf16(v, h, l);
    hi[t] = h; lo[t] = l;
}

// ---- prep: ALL weights transpose+split in one launch ------------------------
__global__ void prep_all(const float* __restrict__ W0, const float* __restrict__ W1,
                         const float* __restrict__ W2, const float* __restrict__ SW0,
                         const float* __restrict__ SW1,
                         __nv_bfloat16* __restrict__ hi, __nv_bfloat16* __restrict__ lo)
{
    int t = blockIdx.x * blockDim.x + threadIdx.x;
    if (t >= 1736704) return;
    const float* src;
    int local, Kd, Nd;
    unsigned int dbase;
    if (t < 294912) {
        if (t < 32768) { src = W0; local = t; Kd = 64; Nd = 512; dbase = OFF_W0; }
        else           { src = W1; local = t - 32768; Kd = 512; Nd = 512; dbase = OFF_W1; }
    } else if (t < 557056) {
        src = W2; local = t - 294912; Kd = 512; Nd = 512; dbase = OFF_W2;
    } else if (t < 1343488) {
        int u = t - 557056;
        int p = u / 262144;
        local = u - p * 262144;
        src = SW0 + (size_t)p * 262144; Kd = 512; Nd = 512;
        dbase = OFF_SW0 + (unsigned int)p * 262144u;
    } else {
        int u = t - 1343488;
        int p = u / 131072;
        local = u - p * 131072;
        src = SW1 + (size_t)p * 131072; Kd = 512; Nd = 256;
        dbase = OFF_SW1 + (unsigned int)p * 131072u;
    }
    int k = local / Nd, n = local % Nd;
    float v = src[local];
    __nv_bfloat16 h, l;
    split_bf16(v, h, l);
    size_t d = (size_t)dbase + (size_t)n * Kd + k;
    hi[d] = h; lo[d] = l;
}

// ---- final: logit = (hi+lo) . SW2[p] + Sb2[p]; sigmoid/clip/ratio/mask ------
__global__ void subnet_final(const __nv_bfloat16* __restrict__ s1h,
                             const __nv_bfloat16* __restrict__ s1l,
                             const float* __restrict__ SW2,
                             const float* __restrict__ Sb2,
                             const int*   __restrict__ y,
                             const int*   __restrict__ pairs,
                             int p,
                             float* __restrict__ out_r,
                             float* __restrict__ out_s,
                             float* __restrict__ out_m,
                             int Nrows)
{
    __shared__ float w[256];
    const int tid = threadIdx.x;
    w[tid] = SW2[p * 256 + tid];
    __syncthreads();

    const float sb = Sb2[p];
    const int pa = pairs[2 * p + 0];
    const int pb = pairs[2 * p + 1];

    const int lane = tid & 31;
    const int warp = tid >> 5;
    const int gw = blockIdx.x * (blockDim.x >> 5) + warp;
    const int warps_total = gridDim.x * (blockDim.x >> 5);

    for (int n = gw; n < Nrows; n += warps_total) {
        const size_t base = (size_t)n * 256;
        float acc = 0.f;
#pragma unroll
        for (int j = 0; j < 8; j++) {
            int c = lane + 32 * j;
            float v = __bfloat162float(s1h[base + c]) + __bfloat162float(s1l[base + c]);
            acc += v * w[c];
        }
#pragma unroll
        for (int o = 16; o > 0; o >>= 1)
            acc += __shfl_xor_sync(0xFFFFFFFFu, acc, o);

        if (lane == 0) {
            float logit = acc + sb;
            float s = 1.f / (1.f + expf(-logit));
            s = fmaxf(s, 1e-9f);
            float r = (1.f - s) / s;
            int yv = y[n];
            float m = (yv == pa || yv == pb) ? 1.f : 0.f;
            out_r[n] = r * m;
            out_s[n] = s * m;
            out_m[n] = m;
        }
    }
}

// ============================================================================
extern "C" void kernel_launch(void* const* d_in, const int* in_sizes, int n_in,
                              void* d_out, int out_size)
{
    const float* x     = (const float*)d_in[0];
    const int*   y     = (const int*)  d_in[1];
    const int*   pairs = (const int*)  d_in[2];
    const float* W0    = (const float*)d_in[3];
    const float* b0    = (const float*)d_in[4];
    const float* W1    = (const float*)d_in[5];
    const float* b1    = (const float*)d_in[6];
    const float* W2    = (const float*)d_in[7];
    const float* b2    = (const float*)d_in[8];
    const float* SW0   = (const float*)d_in[9];
    const float* Sb0   = (const float*)d_in[10];
    const float* SW1   = (const float*)d_in[11];
    const float* Sb1   = (const float*)d_in[12];
    const float* SW2   = (const float*)d_in[13];
    const float* Sb2   = (const float*)d_in[14];

    const int M = GN;
    float* out   = (float*)d_out;
    float* repr  = out;
    float* r_seg = out + (size_t)M * 512;
    float* s_seg = r_seg + 3 * (size_t)M;
    float* m_seg = s_seg + 3 * (size_t)M;

    __nv_bfloat16 *hiA, *loA, *hiB, *loB, *hiC, *loC, *hiX, *loX, *whi, *wlo;
    cudaGetSymbolAddress((void**)&hiA, g_hiA);
    cudaGetSymbolAddress((void**)&loA, g_loA);
    cudaGetSymbolAddress((void**)&hiB, g_hiB);
    cudaGetSymbolAddress((void**)&loB, g_loB);
    cudaGetSymbolAddress((void**)&hiC, g_hiC);
    cudaGetSymbolAddress((void**)&loC, g_loC);
    cudaGetSymbolAddress((void**)&hiX, g_hiX);
    cudaGetSymbolAddress((void**)&loX, g_loX);
    cudaGetSymbolAddress((void**)&whi, g_whi);
    cudaGetSymbolAddress((void**)&wlo, g_wlo);

    cudaFuncSetAttribute(gemm_mma, cudaFuncAttributeMaxDynamicSharedMemorySize,
                         2 * STAGE_BYTES);

    prep_split_relu<<<(M * 64 + 255) / 256, 256>>>(x, hiX, loX, M * 64);
    prep_all<<<(1736704 + 255) / 256, 256>>>(W0, W1, W2, SW0, SW1, whi, wlo);

    dim3 blk(256);
    dim3 g512(4, M / 128);
    dim3 g256(2, M / 128);
    const size_t shmem = 2 * STAGE_BYTES;

    // trunk
    gemm_mma<<<g512, blk, shmem>>>(hiX, loX, whi + OFF_W0, wlo + OFF_W0, b0,
                                   nullptr, hiA, loA, 64, 512, 0);
    gemm_mma<<<g512, blk, shmem>>>(hiA, loA, whi + OFF_W1, wlo + OFF_W1, b1,
                                   nullptr, hiB, loB, 512, 512, 0);
    gemm_mma<<<g512, blk, shmem>>>(hiB, loB, whi + OFF_W2, wlo + OFF_W2, b2,
                                   repr, hiA, loA, 512, 512, 1);

    // subnets
    for (int p = 0; p < 3; p++) {
        gemm_mma<<<g512, blk, shmem>>>(hiA, loA,
            whi + OFF_SW0 + p * 262144u, wlo + OFF_SW0 + p * 262144u,
            Sb0 + p * 512, nullptr, hiB, loB, 512, 512, 0);
        gemm_mma<<<g256, blk, shmem>>>(hiB, loB,
            whi + OFF_SW1 + p * 131072u, wlo + OFF_SW1 + p * 131072u,
            Sb1 + p * 256, nullptr, hiC, loC, 512, 256, 0);
        subnet_final<<<512, 256>>>(hiC, loC, SW2, Sb2, y, pairs, p,
                                   r_seg + (size_t)p * M,
                                   s_seg + (size_t)p * M,
                                   m_seg + (size_t)p * M, M);
    }
}

// round 8
// speedup vs baseline: 1.2211x; 1.2211x over previous
#include <cuda_runtime.h>
#include <cuda_bf16.h>
#include <cstdint>
#include <math.h>

// ============================================================================
// EnsembleRatioModel — round 7: R6 ldmatrix kernel + __launch_bounds__(256, 2).
// R6 regressed because 132 regs dropped residency to 1 CTA/SM (R4's 122-reg
// scalar version ran 2 CTAs/SM). Force 2 CTAs/SM to overlap sync bubbles.
//
// Output packing (validated): [N*512) repr_ ; [3N) r*m ; [3N) s*m ; [3N) m
// ============================================================================

#define GN 131072

__device__ unsigned short g_hiA[GN * 512];
__device__ unsigned short g_loA[GN * 512];
__device__ unsigned short g_hiB[GN * 512];
__device__ unsigned short g_loB[GN * 512];
__device__ unsigned short g_hiC[GN * 256];
__device__ unsigned short g_loC[GN * 256];
__device__ unsigned short g_hiX[GN * 64];
__device__ unsigned short g_loX[GN * 64];
__device__ unsigned short g_whi[1736704];
__device__ unsigned short g_wlo[1736704];

#define OFF_W0   0u
#define OFF_W1   32768u
#define OFF_W2   294912u
#define OFF_SW0  557056u      /* + p*262144 */
#define OFF_SW1  1343488u     /* + p*131072 */

// ---------------- helpers ----------------------------------------------------
__device__ __forceinline__ uint32_t smem_u32(const void* p) {
    uint32_t a;
    asm("{ .reg .u64 t; cvta.to.shared.u64 t, %1; cvt.u32.u64 %0, t; }"
        : "=r"(a) : "l"(p));
    return a;
}
__device__ __forceinline__ void cpasync16(uint32_t dst, const void* src) {
    asm volatile("cp.async.cg.shared.global [%0], [%1], 16;"
                 :: "r"(dst), "l"(src) : "memory");
}
__device__ __forceinline__ void ldsm_x4(uint32_t* r, uint32_t addr) {
    asm volatile("ldmatrix.sync.aligned.m8n8.x4.shared.b16 {%0,%1,%2,%3}, [%4];"
                 : "=r"(r[0]), "=r"(r[1]), "=r"(r[2]), "=r"(r[3]) : "r"(addr));
}
__device__ __forceinline__ void mma_bf16(float* d, const uint32_t* a,
                                         const uint32_t* b) {
    asm volatile(
        "mma.sync.aligned.m16n8k16.row.col.f32.bf16.bf16.f32 "
        "{%0,%1,%2,%3}, {%4,%5,%6,%7}, {%8,%9}, {%0,%1,%2,%3};"
        : "+f"(d[0]), "+f"(d[1]), "+f"(d[2]), "+f"(d[3])
        : "r"(a[0]), "r"(a[1]), "r"(a[2]), "r"(a[3]), "r"(b[0]), "r"(b[1]));
}
__device__ __forceinline__ void split_bf16(float v, __nv_bfloat16& h, __nv_bfloat16& l) {
    h = __float2bfloat16(v);
    l = __float2bfloat16(v - __bfloat162float(h));
}

// ============================================================================
// GEMM: C[M,Ntot] = (Ahi+Alo)[M,K] @ (Whi+Wlo)^T   (W stored [Ntot,K])
// 128x128 CTA tile, 256 threads, warp tile 64x32, K-chunk 32, double buffer.
// SMEM per stage: 4 components x 128 rows x 40 bf16 (pitch 80B) = 40960 B.
// ============================================================================
#define STAGE_BYTES 40960
#define COMP_BYTES  10240
#define ROW_PITCH   80

__global__ void __launch_bounds__(256, 2)
gemm_mma(const __nv_bfloat16* __restrict__ Ahi, const __nv_bfloat16* __restrict__ Alo,
         const __nv_bfloat16* __restrict__ Whi, const __nv_bfloat16* __restrict__ Wlo,
         const float* __restrict__ bias,
         float* __restrict__ raw_out,
         __nv_bfloat16* __restrict__ Ohi, __nv_bfloat16* __restrict__ Olo,
         int K, int Ntot, int write_raw)
{
    extern __shared__ __align__(16) char smem[];
    const uint32_t smem_base = smem_u32(smem);

    const int tid   = threadIdx.x;
    const int wid   = tid >> 5;
    const int lane  = tid & 31;
    const int g     = lane >> 2;
    const int tk    = lane & 3;
    const int warpM = wid >> 2;       // 0..1 -> 64-row half
    const int warpN = wid & 3;        // 0..3 -> 32-col quarter
    const int m0 = blockIdx.y * 128;
    const int n0 = blockIdx.x * 128;

    const int nk = K >> 5;

    // ldmatrix lane-address components
    const uint32_t a_lrow = (uint32_t)(lane & 15) * ROW_PITCH + (uint32_t)(lane >> 4) * 16;
    const uint32_t b_lrow = (uint32_t)((lane & 7) + ((lane >> 4) << 3)) * ROW_PITCH
                          + (uint32_t)((lane >> 3) & 1) * 16;

    auto load_chunk = [&](int c, int s) {
        const uint32_t st = smem_base + (uint32_t)s * STAGE_BYTES;
        const int koff = c * 32;
#pragma unroll
        for (int i = 0; i < 8; i++) {
            int idx  = i * 256 + tid;
            int comp = idx >> 9;
            int rem  = idx & 511;
            int row  = rem >> 2;
            int seg  = rem & 3;
            uint32_t dst = st + (uint32_t)comp * COMP_BYTES
                         + (uint32_t)row * ROW_PITCH + (uint32_t)seg * 16;
            const __nv_bfloat16* src;
            size_t roff;
            if (comp == 0)      { src = Ahi; roff = (size_t)(m0 + row) * K; }
            else if (comp == 1) { src = Alo; roff = (size_t)(m0 + row) * K; }
            else if (comp == 2) { src = Whi; roff = (size_t)(n0 + row) * K; }
            else                { src = Wlo; roff = (size_t)(n0 + row) * K; }
            cpasync16(dst, src + roff + koff + seg * 8);
        }
        asm volatile("cp.async.commit_group;" ::: "memory");
    };

    float acc[4][4][4];
#pragma unroll
    for (int i = 0; i < 4; i++)
#pragma unroll
        for (int j = 0; j < 4; j++)
#pragma unroll
            for (int r = 0; r < 4; r++) acc[i][j][r] = 0.f;

    load_chunk(0, 0);

    for (int c = 0; c < nk; c++) {
        if (c + 1 < nk) {
            load_chunk(c + 1, (c + 1) & 1);
            asm volatile("cp.async.wait_group 1;" ::: "memory");
        } else {
            asm volatile("cp.async.wait_group 0;" ::: "memory");
        }
        __syncthreads();

        const uint32_t sb = smem_base + (uint32_t)(c & 1) * STAGE_BYTES;
        const uint32_t aBase = sb + (uint32_t)(warpM * 64) * ROW_PITCH;
        const uint32_t bBase = sb + 2u * COMP_BYTES + (uint32_t)(warpN * 32) * ROW_PITCH;

#pragma unroll
        for (int t = 0; t < 2; t++) {
            const uint32_t kb = (uint32_t)t * 32;

            // B fragments: 2 x ldsm_x4 hi, 2 x lo
            uint32_t bh[4][2], bl[4][2];
#pragma unroll
            for (int jj = 0; jj < 2; jj++) {
                uint32_t r4[4];
                uint32_t addr = bBase + (uint32_t)(jj * 16) * ROW_PITCH + kb + b_lrow;
                ldsm_x4(r4, addr);
                bh[jj * 2][0] = r4[0]; bh[jj * 2][1] = r4[1];
                bh[jj * 2 + 1][0] = r4[2]; bh[jj * 2 + 1][1] = r4[3];
                ldsm_x4(r4, addr + COMP_BYTES);
                bl[jj * 2][0] = r4[0]; bl[jj * 2][1] = r4[1];
                bl[jj * 2 + 1][0] = r4[2]; bl[jj * 2 + 1][1] = r4[3];
            }
            // A hi fragments
            uint32_t ah[4][4];
#pragma unroll
            for (int i = 0; i < 4; i++)
                ldsm_x4(ah[i], aBase + (uint32_t)(i * 16) * ROW_PITCH + kb + a_lrow);

#pragma unroll
            for (int i = 0; i < 4; i++)
#pragma unroll
                for (int j = 0; j < 4; j++) {
                    mma_bf16(acc[i][j], ah[i], bh[j]);
                    mma_bf16(acc[i][j], ah[i], bl[j]);
                }
            // A lo fragments (reuse ah registers via separate array; compiler
            // may overlap — launch_bounds caps regs at 128)
            uint32_t al[4][4];
#pragma unroll
            for (int i = 0; i < 4; i++)
                ldsm_x4(al[i], aBase + COMP_BYTES + (uint32_t)(i * 16) * ROW_PITCH + kb + a_lrow);
#pragma unroll
            for (int i = 0; i < 4; i++)
#pragma unroll
                for (int j = 0; j < 4; j++)
                    mma_bf16(acc[i][j], al[i], bh[j]);
        }
        __syncthreads();
    }

    // ---- epilogue -----------------------------------------------------------
#pragma unroll
    for (int j = 0; j < 4; j++) {
        const int cc = n0 + warpN * 32 + j * 8 + tk * 2;
        const float b0v = bias[cc];
        const float b1v = bias[cc + 1];
#pragma unroll
        for (int i = 0; i < 4; i++) {
            const int r0 = m0 + warpM * 64 + i * 16 + g;
#pragma unroll
            for (int half = 0; half < 2; half++) {
                const int r = r0 + half * 8;
                float v0 = acc[i][j][half * 2 + 0] + b0v;
                float v1 = acc[i][j][half * 2 + 1] + b1v;
                const size_t off = (size_t)r * Ntot + cc;
                if (write_raw)
                    *(float2*)(raw_out + off) = make_float2(v0, v1);
                v0 = fmaxf(v0, 0.f);
                v1 = fmaxf(v1, 0.f);
                __nv_bfloat16 h0, l0, h1, l1;
                split_bf16(v0, h0, l0);
                split_bf16(v1, h1, l1);
                uint32_t hp = (uint32_t)__bfloat16_as_ushort(h0)
                            | ((uint32_t)__bfloat16_as_ushort(h1) << 16);
                uint32_t lp = (uint32_t)__bfloat16_as_ushort(l0)
                            | ((uint32_t)__bfloat16_as_ushort(l1) << 16);
                *(uint32_t*)(Ohi + off) = hp;
                *(uint32_t*)(Olo + off) = lp;
            }
        }
    }
}

// ---- prep: relu + bf16 hi/lo split of x -------------------------------------
__global__ void prep_split_relu(const float* __restrict__ src,
                                __nv_bfloat16* __restrict__ hi,
                                __nv_bfloat16* __restrict__ lo, int n)
{
    int t = blockIdx.x * blockDim.x + threadIdx.x;
    if (t >= n) return;
    float v = fmaxf(src[t], 0.0f);
    __nv_bfloat16 h, l;
    split_bf16(v, h, l);
    hi[t] = h; lo[t] = l;
}

// ---- prep: ALL weights transpose+split in one launch ------------------------
__global__ void prep_all(const float* __restrict__ W0, const float* __restrict__ W1,
                         const float* __restrict__ W2, const float* __restrict__ SW0,
                         const float* __restrict__ SW1,
                         __nv_bfloat16* __restrict__ hi, __nv_bfloat16* __restrict__ lo)
{
    int t = blockIdx.x * blockDim.x + threadIdx.x;
    if (t >= 1736704) return;
    const float* src;
    int local, Kd, Nd;
    unsigned int dbase;
    if (t < 294912) {
        if (t < 32768) { src = W0; local = t; Kd = 64; Nd = 512; dbase = OFF_W0; }
        else           { src = W1; local = t - 32768; Kd = 512; Nd = 512; dbase = OFF_W1; }
    } else if (t < 557056) {
        src = W2; local = t - 294912; Kd = 512; Nd = 512; dbase = OFF_W2;
    } else if (t < 1343488) {
        int u = t - 557056;
        int p = u / 262144;
        local = u - p * 262144;
        src = SW0 + (size_t)p * 262144; Kd = 512; Nd = 512;
        dbase = OFF_SW0 + (unsigned int)p * 262144u;
    } else {
        int u = t - 1343488;
        int p = u / 131072;
        local = u - p * 131072;
        src = SW1 + (size_t)p * 131072; Kd = 512; Nd = 256;
        dbase = OFF_SW1 + (unsigned int)p * 131072u;
    }
    int k = local / Nd, n = local % Nd;
    float v = src[local];
    __nv_bfloat16 h, l;
    split_bf16(v, h, l);
    size_t d = (size_t)dbase + (size_t)n * Kd + k;
    hi[d] = h; lo[d] = l;
}

// ---- final: logit = (hi+lo) . SW2[p] + Sb2[p]; sigmoid/clip/ratio/mask ------
__global__ void subnet_final(const __nv_bfloat16* __restrict__ s1h,
                             const __nv_bfloat16* __restrict__ s1l,
                             const float* __restrict__ SW2,
                             const float* __restrict__ Sb2,
                             const int*   __restrict__ y,
                             const int*   __restrict__ pairs,
                             int p,
                             float* __restrict__ out_r,
                             float* __restrict__ out_s,
                             float* __restrict__ out_m,
                             int Nrows)
{
    __shared__ float w[256];
    const int tid = threadIdx.x;
    w[tid] = SW2[p * 256 + tid];
    __syncthreads();

    const float sb = Sb2[p];
    const int pa = pairs[2 * p + 0];
    const int pb = pairs[2 * p + 1];

    const int lane = tid & 31;
    const int warp = tid >> 5;
    const int gw = blockIdx.x * (blockDim.x >> 5) + warp;
    const int warps_total = gridDim.x * (blockDim.x >> 5);

    for (int n = gw; n < Nrows; n += warps_total) {
        const size_t base = (size_t)n * 256;
        float acc = 0.f;
#pragma unroll
        for (int j = 0; j < 8; j++) {
            int c = lane + 32 * j;
            float v = __bfloat162float(s1h[base + c]) + __bfloat162float(s1l[base + c]);
            acc += v * w[c];
        }
#pragma unroll
        for (int o = 16; o > 0; o >>= 1)
            acc += __shfl_xor_sync(0xFFFFFFFFu, acc, o);

        if (lane == 0) {
            float logit = acc + sb;
            float s = 1.f / (1.f + expf(-logit));
            s = fmaxf(s, 1e-9f);
            float r = (1.f - s) / s;
            int yv = y[n];
            float m = (yv == pa || yv == pb) ? 1.f : 0.f;
            out_r[n] = r * m;
            out_s[n] = s * m;
            out_m[n] = m;
        }
    }
}

// ============================================================================
extern "C" void kernel_launch(void* const* d_in, const int* in_sizes, int n_in,
                              void* d_out, int out_size)
{
    const float* x     = (const float*)d_in[0];
    const int*   y     = (const int*)  d_in[1];
    const int*   pairs = (const int*)  d_in[2];
    const float* W0    = (const float*)d_in[3];
    const float* b0    = (const float*)d_in[4];
    const float* W1    = (const float*)d_in[5];
    const float* b1    = (const float*)d_in[6];
    const float* W2    = (const float*)d_in[7];
    const float* b2    = (const float*)d_in[8];
    const float* SW0   = (const float*)d_in[9];
    const float* Sb0   = (const float*)d_in[10];
    const float* SW1   = (const float*)d_in[11];
    const float* Sb1   = (const float*)d_in[12];
    const float* SW2   = (const float*)d_in[13];
    const float* Sb2   = (const float*)d_in[14];

    const int M = GN;
    float* out   = (float*)d_out;
    float* repr  = out;
    float* r_seg = out + (size_t)M * 512;
    float* s_seg = r_seg + 3 * (size_t)M;
    float* m_seg = s_seg + 3 * (size_t)M;

    __nv_bfloat16 *hiA, *loA, *hiB, *loB, *hiC, *loC, *hiX, *loX, *whi, *wlo;
    cudaGetSymbolAddress((void**)&hiA, g_hiA);
    cudaGetSymbolAddress((void**)&loA, g_loA);
    cudaGetSymbolAddress((void**)&hiB, g_hiB);
    cudaGetSymbolAddress((void**)&loB, g_loB);
    cudaGetSymbolAddress((void**)&hiC, g_hiC);
    cudaGetSymbolAddress((void**)&loC, g_loC);
    cudaGetSymbolAddress((void**)&hiX, g_hiX);
    cudaGetSymbolAddress((void**)&loX, g_loX);
    cudaGetSymbolAddress((void**)&whi, g_whi);
    cudaGetSymbolAddress((void**)&wlo, g_wlo);

    cudaFuncSetAttribute(gemm_mma, cudaFuncAttributeMaxDynamicSharedMemorySize,
                         2 * STAGE_BYTES);

    prep_split_relu<<<(M * 64 + 255) / 256, 256>>>(x, hiX, loX, M * 64);
    prep_all<<<(1736704 + 255) / 256, 256>>>(W0, W1, W2, SW0, SW1, whi, wlo);

    dim3 blk(256);
    dim3 g512(4, M / 128);
    dim3 g256(2, M / 128);
    const size_t shmem = 2 * STAGE_BYTES;

    // trunk
    gemm_mma<<<g512, blk, shmem>>>(hiX, loX, whi + OFF_W0, wlo + OFF_W0, b0,
                                   nullptr, hiA, loA, 64, 512, 0);
    gemm_mma<<<g512, blk, shmem>>>(hiA, loA, whi + OFF_W1, wlo + OFF_W1, b1,
                                   nullptr, hiB, loB, 512, 512, 0);
    gemm_mma<<<g512, blk, shmem>>>(hiB, loB, whi + OFF_W2, wlo + OFF_W2, b2,
                                   repr, hiA, loA, 512, 512, 1);

    // subnets
    for (int p = 0; p < 3; p++) {
        gemm_mma<<<g512, blk, shmem>>>(hiA, loA,
            whi + OFF_SW0 + p * 262144u, wlo + OFF_SW0 + p * 262144u,
            Sb0 + p * 512, nullptr, hiB, loB, 512, 512, 0);
        gemm_mma<<<g256, blk, shmem>>>(hiB, loB,
            whi + OFF_SW1 + p * 131072u, wlo + OFF_SW1 + p * 131072u,
            Sb1 + p * 256, nullptr, hiC, loC, 512, 256, 0);
        subnet_final<<<512, 256>>>(hiC, loC, SW2, Sb2, y, pairs, p,
                                   r_seg + (size_t)p * M,
                                   s_seg + (size_t)p * M,
                                   m_seg + (size_t)p * M, M);
    }
}

// round 9
// speedup vs baseline: 1.5223x; 1.2466x over previous
#include <cuda_runtime.h>
#include <cuda_bf16.h>
#include <cstdint>
#include <math.h>

// ============================================================================
// EnsembleRatioModel — round 8: R7 kernel + masked-row compaction for subnets.
// Each pair p only needs rows with y in pair (≈2/3 of N). SW0 gathers rows via
// an index list inside its cp.async loader (no gather pass); SW1/final run on
// the packed buffer; subnet_final scatters to original rows. r/s/m pre-zeroed.
//
// Output packing (validated): [N*512) repr_ ; [3N) r*m ; [3N) s*m ; [3N) m
// ============================================================================

#define GN 131072

__device__ unsigned short g_hiA[GN * 512];
__device__ unsigned short g_loA[GN * 512];
__device__ unsigned short g_hiB[GN * 512];
__device__ unsigned short g_loB[GN * 512];
__device__ unsigned short g_hiC[GN * 256];
__device__ unsigned short g_loC[GN * 256];
__device__ unsigned short g_hiX[GN * 64];
__device__ unsigned short g_loX[GN * 64];
__device__ unsigned short g_whi[1736704];
__device__ unsigned short g_wlo[1736704];

// per-pair row compaction state
__device__ int g_cnt[4];        // raw member counts per pair
__device__ int g_cntpad[4];     // counts rounded up to 128
__device__ int g_idx[3 * (GN + 128)];

#define IDX_STRIDE (GN + 128)

#define OFF_W0   0u
#define OFF_W1   32768u
#define OFF_W2   294912u
#define OFF_SW0  557056u      /* + p*262144 */
#define OFF_SW1  1343488u     /* + p*131072 */

// ---------------- helpers ----------------------------------------------------
__device__ __forceinline__ uint32_t smem_u32(const void* p) {
    uint32_t a;
    asm("{ .reg .u64 t; cvta.to.shared.u64 t, %1; cvt.u32.u64 %0, t; }"
        : "=r"(a) : "l"(p));
    return a;
}
__device__ __forceinline__ void cpasync16(uint32_t dst, const void* src) {
    asm volatile("cp.async.cg.shared.global [%0], [%1], 16;"
                 :: "r"(dst), "l"(src) : "memory");
}
__device__ __forceinline__ void ldsm_x4(uint32_t* r, uint32_t addr) {
    asm volatile("ldmatrix.sync.aligned.m8n8.x4.shared.b16 {%0,%1,%2,%3}, [%4];"
                 : "=r"(r[0]), "=r"(r[1]), "=r"(r[2]), "=r"(r[3]) : "r"(addr));
}
__device__ __forceinline__ void mma_bf16(float* d, const uint32_t* a,
                                         const uint32_t* b) {
    asm volatile(
        "mma.sync.aligned.m16n8k16.row.col.f32.bf16.bf16.f32 "
        "{%0,%1,%2,%3}, {%4,%5,%6,%7}, {%8,%9}, {%0,%1,%2,%3};"
        : "+f"(d[0]), "+f"(d[1]), "+f"(d[2]), "+f"(d[3])
        : "r"(a[0]), "r"(a[1]), "r"(a[2]), "r"(a[3]), "r"(b[0]), "r"(b[1]));
}
__device__ __forceinline__ void split_bf16(float v, __nv_bfloat16& h, __nv_bfloat16& l) {
    h = __float2bfloat16(v);
    l = __float2bfloat16(v - __bfloat162float(h));
}

// ============================================================================
// GEMM: C[M,Ntot] = (Ahi+Alo)[M,K] @ (Whi+Wlo)^T   (W stored [Ntot,K])
// 128x128 CTA tile, 256 threads, warp tile 64x32, K-chunk 32, double buffer.
// Optional row_idx: A rows gathered via index list; outputs written packed.
// Optional cntpad: device row-count for early exit (grid is worst-case sized).
// ============================================================================
#define STAGE_BYTES 40960
#define COMP_BYTES  10240
#define ROW_PITCH   80

__global__ void __launch_bounds__(256, 2)
gemm_mma(const __nv_bfloat16* __restrict__ Ahi, const __nv_bfloat16* __restrict__ Alo,
         const __nv_bfloat16* __restrict__ Whi, const __nv_bfloat16* __restrict__ Wlo,
         const float* __restrict__ bias,
         float* __restrict__ raw_out,
         __nv_bfloat16* __restrict__ Ohi, __nv_bfloat16* __restrict__ Olo,
         int K, int Ntot, int write_raw,
         const int* __restrict__ row_idx, const int* __restrict__ cntpad)
{
    extern __shared__ __align__(16) char smem[];
    const uint32_t smem_base = smem_u32(smem);

    const int m0 = blockIdx.y * 128;
    if (cntpad && m0 >= __ldg(cntpad)) return;   // uniform early exit
    const int n0 = blockIdx.x * 128;

    const int tid   = threadIdx.x;
    const int wid   = tid >> 5;
    const int lane  = tid & 31;
    const int g     = lane >> 2;
    const int tk    = lane & 3;
    const int warpM = wid >> 2;
    const int warpN = wid & 3;

    const int nk = K >> 5;

    const uint32_t a_lrow = (uint32_t)(lane & 15) * ROW_PITCH + (uint32_t)(lane >> 4) * 16;
    const uint32_t b_lrow = (uint32_t)((lane & 7) + ((lane >> 4) << 3)) * ROW_PITCH
                          + (uint32_t)((lane >> 3) & 1) * 16;

    auto load_chunk = [&](int c, int s) {
        const uint32_t st = smem_base + (uint32_t)s * STAGE_BYTES;
        const int koff = c * 32;
#pragma unroll
        for (int i = 0; i < 8; i++) {
            int idx  = i * 256 + tid;
            int comp = idx >> 9;
            int rem  = idx & 511;
            int row  = rem >> 2;
            int seg  = rem & 3;
            uint32_t dst = st + (uint32_t)comp * COMP_BYTES
                         + (uint32_t)row * ROW_PITCH + (uint32_t)seg * 16;
            const __nv_bfloat16* src;
            size_t roff;
            if (comp <= 1) {
                int gr = m0 + row;
                if (row_idx) gr = __ldg(&row_idx[gr]);
                src = (comp == 0) ? Ahi : Alo;
                roff = (size_t)gr * K;
            } else if (comp == 2) { src = Whi; roff = (size_t)(n0 + row) * K; }
            else                  { src = Wlo; roff = (size_t)(n0 + row) * K; }
            cpasync16(dst, src + roff + koff + seg * 8);
        }
        asm volatile("cp.async.commit_group;" ::: "memory");
    };

    float acc[4][4][4];
#pragma unroll
    for (int i = 0; i < 4; i++)
#pragma unroll
        for (int j = 0; j < 4; j++)
#pragma unroll
            for (int r = 0; r < 4; r++) acc[i][j][r] = 0.f;

    load_chunk(0, 0);

    for (int c = 0; c < nk; c++) {
        if (c + 1 < nk) {
            load_chunk(c + 1, (c + 1) & 1);
            asm volatile("cp.async.wait_group 1;" ::: "memory");
        } else {
            asm volatile("cp.async.wait_group 0;" ::: "memory");
        }
        __syncthreads();

        const uint32_t sb = smem_base + (uint32_t)(c & 1) * STAGE_BYTES;
        const uint32_t aBase = sb + (uint32_t)(warpM * 64) * ROW_PITCH;
        const uint32_t bBase = sb + 2u * COMP_BYTES + (uint32_t)(warpN * 32) * ROW_PITCH;

#pragma unroll
        for (int t = 0; t < 2; t++) {
            const uint32_t kb = (uint32_t)t * 32;

            uint32_t bh[4][2], bl[4][2];
#pragma unroll
            for (int jj = 0; jj < 2; jj++) {
                uint32_t r4[4];
                uint32_t addr = bBase + (uint32_t)(jj * 16) * ROW_PITCH + kb + b_lrow;
                ldsm_x4(r4, addr);
                bh[jj * 2][0] = r4[0]; bh[jj * 2][1] = r4[1];
                bh[jj * 2 + 1][0] = r4[2]; bh[jj * 2 + 1][1] = r4[3];
                ldsm_x4(r4, addr + COMP_BYTES);
                bl[jj * 2][0] = r4[0]; bl[jj * 2][1] = r4[1];
                bl[jj * 2 + 1][0] = r4[2]; bl[jj * 2 + 1][1] = r4[3];
            }
            uint32_t ah[4][4];
#pragma unroll
            for (int i = 0; i < 4; i++)
                ldsm_x4(ah[i], aBase + (uint32_t)(i * 16) * ROW_PITCH + kb + a_lrow);

#pragma unroll
            for (int i = 0; i < 4; i++)
#pragma unroll
                for (int j = 0; j < 4; j++) {
                    mma_bf16(acc[i][j], ah[i], bh[j]);
                    mma_bf16(acc[i][j], ah[i], bl[j]);
                }
            uint32_t al[4][4];
#pragma unroll
            for (int i = 0; i < 4; i++)
                ldsm_x4(al[i], aBase + COMP_BYTES + (uint32_t)(i * 16) * ROW_PITCH + kb + a_lrow);
#pragma unroll
            for (int i = 0; i < 4; i++)
#pragma unroll
                for (int j = 0; j < 4; j++)
                    mma_bf16(acc[i][j], al[i], bh[j]);
        }
        __syncthreads();
    }

    // ---- epilogue (writes packed rows m0+row) ------------------------------
#pragma unroll
    for (int j = 0; j < 4; j++) {
        const int cc = n0 + warpN * 32 + j * 8 + tk * 2;
        const float b0v = bias[cc];
        const float b1v = bias[cc + 1];
#pragma unroll
        for (int i = 0; i < 4; i++) {
            const int r0 = m0 + warpM * 64 + i * 16 + g;
#pragma unroll
            for (int half = 0; half < 2; half++) {
                const int r = r0 + half * 8;
                float v0 = acc[i][j][half * 2 + 0] + b0v;
                float v1 = acc[i][j][half * 2 + 1] + b1v;
                const size_t off = (size_t)r * Ntot + cc;
                if (write_raw)
                    *(float2*)(raw_out + off) = make_float2(v0, v1);
                v0 = fmaxf(v0, 0.f);
                v1 = fmaxf(v1, 0.f);
                __nv_bfloat16 h0, l0, h1, l1;
                split_bf16(v0, h0, l0);
                split_bf16(v1, h1, l1);
                uint32_t hp = (uint32_t)__bfloat16_as_ushort(h0)
                            | ((uint32_t)__bfloat16_as_ushort(h1) << 16);
                uint32_t lp = (uint32_t)__bfloat16_as_ushort(l0)
                            | ((uint32_t)__bfloat16_as_ushort(l1) << 16);
                *(uint32_t*)(Ohi + off) = hp;
                *(uint32_t*)(Olo + off) = lp;
            }
        }
    }
}

// ---- prep: relu + bf16 hi/lo split of x -------------------------------------
__global__ void prep_split_relu(const float* __restrict__ src,
                                __nv_bfloat16* __restrict__ hi,
                                __nv_bfloat16* __restrict__ lo, int n)
{
    int t = blockIdx.x * blockDim.x + threadIdx.x;
    if (t >= n) return;
    float v = fmaxf(src[t], 0.0f);
    __nv_bfloat16 h, l;
    split_bf16(v, h, l);
    hi[t] = h; lo[t] = l;
}

// ---- prep: ALL weights transpose+split in one launch ------------------------
__global__ void prep_all(const float* __restrict__ W0, const float* __restrict__ W1,
                         const float* __restrict__ W2, const float* __restrict__ SW0,
                         const float* __restrict__ SW1,
                         __nv_bfloat16* __restrict__ hi, __nv_bfloat16* __restrict__ lo)
{
    int t = blockIdx.x * blockDim.x + threadIdx.x;
    if (t >= 1736704) return;
    const float* src;
    int local, Kd, Nd;
    unsigned int dbase;
    if (t < 294912) {
        if (t < 32768) { src = W0; local = t; Kd = 64; Nd = 512; dbase = OFF_W0; }
        else           { src = W1; local = t - 32768; Kd = 512; Nd = 512; dbase = OFF_W1; }
    } else if (t < 557056) {
        src = W2; local = t - 294912; Kd = 512; Nd = 512; dbase = OFF_W2;
    } else if (t < 1343488) {
        int u = t - 557056;
        int p = u / 262144;
        local = u - p * 262144;
        src = SW0 + (size_t)p * 262144; Kd = 512; Nd = 512;
        dbase = OFF_SW0 + (unsigned int)p * 262144u;
    } else {
        int u = t - 1343488;
        int p = u / 131072;
        local = u - p * 131072;
        src = SW1 + (size_t)p * 131072; Kd = 512; Nd = 256;
        dbase = OFF_SW1 + (unsigned int)p * 131072u;
    }
    int k = local / Nd, n = local % Nd;
    float v = src[local];
    __nv_bfloat16 h, l;
    split_bf16(v, h, l);
    size_t d = (size_t)dbase + (size_t)n * Kd + k;
    hi[d] = h; lo[d] = l;
}

// ---- index build: per-pair member lists (order-free; values order-invariant)
__global__ void idx_reset() {
    if (threadIdx.x < 4) { g_cnt[threadIdx.x] = 0; g_cntpad[threadIdx.x] = 0; }
}
__global__ void idx_build(const int* __restrict__ y, const int* __restrict__ pairs, int n)
{
    int t = blockIdx.x * blockDim.x + threadIdx.x;
    if (t >= n) return;
    int yv = y[t];
#pragma unroll
    for (int p = 0; p < 3; p++) {
        if (yv == pairs[2 * p] || yv == pairs[2 * p + 1]) {
            int pos = atomicAdd(&g_cnt[p], 1);
            g_idx[p * IDX_STRIDE + pos] = t;
        }
    }
}
__global__ void idx_pad()
{
    int p = blockIdx.x;          // 3 blocks, 128 threads
    int c = g_cnt[p];
    int cp = (c + 127) & ~127;
    for (int i = c + threadIdx.x; i < cp; i += 128)
        g_idx[p * IDX_STRIDE + i] = 0;   // pad with valid row 0 (junk, never used)
    if (threadIdx.x == 0) g_cntpad[p] = cp;
}

// ---- final: packed rows, scatter to original index --------------------------
__global__ void subnet_final(const __nv_bfloat16* __restrict__ s1h,
                             const __nv_bfloat16* __restrict__ s1l,
                             const float* __restrict__ SW2,
                             const float* __restrict__ Sb2,
                             const int*   __restrict__ idxlist,
                             const int*   __restrict__ cnt_ptr,
                             int p,
                             float* __restrict__ out_r,
                             float* __restrict__ out_s,
                             float* __restrict__ out_m)
{
    __shared__ float w[256];
    const int tid = threadIdx.x;
    w[tid] = SW2[p * 256 + tid];
    __syncthreads();

    const float sb = Sb2[p];
    const int limit = __ldg(cnt_ptr);

    const int lane = tid & 31;
    const int warp = tid >> 5;
    const int gw = blockIdx.x * (blockDim.x >> 5) + warp;
    const int warps_total = gridDim.x * (blockDim.x >> 5);

    for (int n = gw; n < limit; n += warps_total) {
        const size_t base = (size_t)n * 256;
        float acc = 0.f;
#pragma unroll
        for (int j = 0; j < 8; j++) {
            int c = lane + 32 * j;
            float v = __bfloat162float(s1h[base + c]) + __bfloat162float(s1l[base + c]);
            acc += v * w[c];
        }
#pragma unroll
        for (int o = 16; o > 0; o >>= 1)
            acc += __shfl_xor_sync(0xFFFFFFFFu, acc, o);

        if (lane == 0) {
            float logit = acc + sb;
            float s = 1.f / (1.f + expf(-logit));
            s = fmaxf(s, 1e-9f);
            float r = (1.f - s) / s;
            int orig = __ldg(&idxlist[n]);
            out_r[orig] = r;
            out_s[orig] = s;
            out_m[orig] = 1.f;
        }
    }
}

// ============================================================================
extern "C" void kernel_launch(void* const* d_in, const int* in_sizes, int n_in,
                              void* d_out, int out_size)
{
    const float* x     = (const float*)d_in[0];
    const int*   y     = (const int*)  d_in[1];
    const int*   pairs = (const int*)  d_in[2];
    const float* W0    = (const float*)d_in[3];
    const float* b0    = (const float*)d_in[4];
    const float* W1    = (const float*)d_in[5];
    const float* b1    = (const float*)d_in[6];
    const float* W2    = (const float*)d_in[7];
    const float* b2    = (const float*)d_in[8];
    const float* SW0   = (const float*)d_in[9];
    const float* Sb0   = (const float*)d_in[10];
    const float* SW1   = (const float*)d_in[11];
    const float* Sb1   = (const float*)d_in[12];
    const float* SW2   = (const float*)d_in[13];
    const float* Sb2   = (const float*)d_in[14];

    const int M = GN;
    float* out   = (float*)d_out;
    float* repr  = out;
    float* r_seg = out + (size_t)M * 512;
    float* s_seg = r_seg + 3 * (size_t)M;
    float* m_seg = s_seg + 3 * (size_t)M;

    __nv_bfloat16 *hiA, *loA, *hiB, *loB, *hiC, *loC, *hiX, *loX, *whi, *wlo;
    cudaGetSymbolAddress((void**)&hiA, g_hiA);
    cudaGetSymbolAddress((void**)&loA, g_loA);
    cudaGetSymbolAddress((void**)&hiB, g_hiB);
    cudaGetSymbolAddress((void**)&loB, g_loB);
    cudaGetSymbolAddress((void**)&hiC, g_hiC);
    cudaGetSymbolAddress((void**)&loC, g_loC);
    cudaGetSymbolAddress((void**)&hiX, g_hiX);
    cudaGetSymbolAddress((void**)&loX, g_loX);
    cudaGetSymbolAddress((void**)&whi, g_whi);
    cudaGetSymbolAddress((void**)&wlo, g_wlo);
    int *idxp, *cntp, *cntpadp;
    cudaGetSymbolAddress((void**)&idxp, g_idx);
    cudaGetSymbolAddress((void**)&cntp, g_cnt);
    cudaGetSymbolAddress((void**)&cntpadp, g_cntpad);

    cudaFuncSetAttribute(gemm_mma, cudaFuncAttributeMaxDynamicSharedMemorySize,
                         2 * STAGE_BYTES);

    // zero subnet output segments (non-members stay exactly 0)
    cudaMemsetAsync(r_seg, 0, 9 * (size_t)M * sizeof(float));

    // prep + index build
    prep_split_relu<<<(M * 64 + 255) / 256, 256>>>(x, hiX, loX, M * 64);
    prep_all<<<(1736704 + 255) / 256, 256>>>(W0, W1, W2, SW0, SW1, whi, wlo);
    idx_reset<<<1, 32>>>();
    idx_build<<<(M + 255) / 256, 256>>>(y, pairs, M);
    idx_pad<<<3, 128>>>();

    dim3 blk(256);
    dim3 g512(4, M / 128);
    dim3 g256(2, M / 128);
    const size_t shmem = 2 * STAGE_BYTES;

    // trunk (dense)
    gemm_mma<<<g512, blk, shmem>>>(hiX, loX, whi + OFF_W0, wlo + OFF_W0, b0,
                                   nullptr, hiA, loA, 64, 512, 0, nullptr, nullptr);
    gemm_mma<<<g512, blk, shmem>>>(hiA, loA, whi + OFF_W1, wlo + OFF_W1, b1,
                                   nullptr, hiB, loB, 512, 512, 0, nullptr, nullptr);
    gemm_mma<<<g512, blk, shmem>>>(hiB, loB, whi + OFF_W2, wlo + OFF_W2, b2,
                                   repr, hiA, loA, 512, 512, 1, nullptr, nullptr);

    // subnets on compacted rows (grids worst-case; device early exit on cntpad)
    for (int p = 0; p < 3; p++) {
        const int* il = idxp + p * IDX_STRIDE;
        gemm_mma<<<g512, blk, shmem>>>(hiA, loA,
            whi + OFF_SW0 + p * 262144u, wlo + OFF_SW0 + p * 262144u,
            Sb0 + p * 512, nullptr, hiB, loB, 512, 512, 0, il, cntpadp + p);
        gemm_mma<<<g256, blk, shmem>>>(hiB, loB,
            whi + OFF_SW1 + p * 131072u, wlo + OFF_SW1 + p * 131072u,
            Sb1 + p * 256, nullptr, hiC, loC, 512, 256, 0, nullptr, cntpadp + p);
        subnet_final<<<512, 256>>>(hiC, loC, SW2, Sb2, il, cntp + p, p,
                                   r_seg + (size_t)p * M,
                                   s_seg + (size_t)p * M,
                                   m_seg + (size_t)p * M);
    }
}

// round 10
// speedup vs baseline: 1.5565x; 1.0225x over previous
#include <cuda_runtime.h>
#include <cuda_bf16.h>
#include <cstdint>
#include <math.h>

// ============================================================================
// EnsembleRatioModel — round 9: R8 + z-batched subnet launches.
// The 3 per-pair chains are independent; merging them into one launch each
// (blockIdx.z = pair) lets the scheduler fill tail waves across pairs and
// removes launch serialization. GEMM mainloop identical to R8.
//
// Output packing (validated): [N*512) repr_ ; [3N) r*m ; [3N) s*m ; [3N) m
// ============================================================================

#define GN 131072

__device__ unsigned short g_hiA[GN * 512];
__device__ unsigned short g_loA[GN * 512];
__device__ unsigned short g_hiB[3ULL * GN * 512];   // per-pair SW0 outputs
__device__ unsigned short g_loB[3ULL * GN * 512];
__device__ unsigned short g_hiC[3ULL * GN * 256];   // per-pair SW1 outputs
__device__ unsigned short g_loC[3ULL * GN * 256];
__device__ unsigned short g_hiX[GN * 64];
__device__ unsigned short g_loX[GN * 64];
__device__ unsigned short g_whi[1736704];
__device__ unsigned short g_wlo[1736704];

// per-pair row compaction state
__device__ int g_cnt[4];
__device__ int g_cntpad[4];
__device__ int g_idx[3 * (GN + 128)];

#define IDX_STRIDE (GN + 128)

#define OFF_W0   0u
#define OFF_W1   32768u
#define OFF_W2   294912u
#define OFF_SW0  557056u      /* + p*262144 */
#define OFF_SW1  1343488u     /* + p*131072 */

// ---------------- helpers ----------------------------------------------------
__device__ __forceinline__ uint32_t smem_u32(const void* p) {
    uint32_t a;
    asm("{ .reg .u64 t; cvta.to.shared.u64 t, %1; cvt.u32.u64 %0, t; }"
        : "=r"(a) : "l"(p));
    return a;
}
__device__ __forceinline__ void cpasync16(uint32_t dst, const void* src) {
    asm volatile("cp.async.cg.shared.global [%0], [%1], 16;"
                 :: "r"(dst), "l"(src) : "memory");
}
__device__ __forceinline__ void ldsm_x4(uint32_t* r, uint32_t addr) {
    asm volatile("ldmatrix.sync.aligned.m8n8.x4.shared.b16 {%0,%1,%2,%3}, [%4];"
                 : "=r"(r[0]), "=r"(r[1]), "=r"(r[2]), "=r"(r[3]) : "r"(addr));
}
__device__ __forceinline__ void mma_bf16(float* d, const uint32_t* a,
                                         const uint32_t* b) {
    asm volatile(
        "mma.sync.aligned.m16n8k16.row.col.f32.bf16.bf16.f32 "
        "{%0,%1,%2,%3}, {%4,%5,%6,%7}, {%8,%9}, {%0,%1,%2,%3};"
        : "+f"(d[0]), "+f"(d[1]), "+f"(d[2]), "+f"(d[3])
        : "r"(a[0]), "r"(a[1]), "r"(a[2]), "r"(a[3]), "r"(b[0]), "r"(b[1]));
}
__device__ __forceinline__ void split_bf16(float v, __nv_bfloat16& h, __nv_bfloat16& l) {
    h = __float2bfloat16(v);
    l = __float2bfloat16(v - __bfloat162float(h));
}

// ============================================================================
// GEMM (z-batched): C = (Ahi+Alo) @ (Whi+Wlo)^T + bias, per z-slice p with
// pointer strides. Optional row gather (row_idx) and device row count (cnt).
// ============================================================================
#define STAGE_BYTES 40960
#define COMP_BYTES  10240
#define ROW_PITCH   80

__global__ void __launch_bounds__(256, 2)
gemm_mma(const __nv_bfloat16* __restrict__ Ahi, const __nv_bfloat16* __restrict__ Alo,
         size_t a_ps,
         const __nv_bfloat16* __restrict__ Whi, const __nv_bfloat16* __restrict__ Wlo,
         size_t w_ps,
         const float* __restrict__ bias, size_t b_ps,
         float* __restrict__ raw_out,
         __nv_bfloat16* __restrict__ Ohi, __nv_bfloat16* __restrict__ Olo,
         size_t o_ps,
         int K, int Ntot, int write_raw,
         const int* __restrict__ row_idx_base, const int* __restrict__ cnt_base)
{
    extern __shared__ __align__(16) char smem[];
    const uint32_t smem_base = smem_u32(smem);

    const int p  = blockIdx.z;
    const int m0 = blockIdx.y * 128;
    if (cnt_base && m0 >= __ldg(cnt_base + p)) return;
    const int n0 = blockIdx.x * 128;

    const int* row_idx = row_idx_base ? row_idx_base + (size_t)p * IDX_STRIDE : nullptr;
    Ahi += (size_t)p * a_ps;  Alo += (size_t)p * a_ps;
    Whi += (size_t)p * w_ps;  Wlo += (size_t)p * w_ps;
    bias += (size_t)p * b_ps;
    Ohi += (size_t)p * o_ps;  Olo += (size_t)p * o_ps;

    const int tid   = threadIdx.x;
    const int wid   = tid >> 5;
    const int lane  = tid & 31;
    const int g     = lane >> 2;
    const int tk    = lane & 3;
    const int warpM = wid >> 2;
    const int warpN = wid & 3;

    const int nk = K >> 5;

    const uint32_t a_lrow = (uint32_t)(lane & 15) * ROW_PITCH + (uint32_t)(lane >> 4) * 16;
    const uint32_t b_lrow = (uint32_t)((lane & 7) + ((lane >> 4) << 3)) * ROW_PITCH
                          + (uint32_t)((lane >> 3) & 1) * 16;

    auto load_chunk = [&](int c, int s) {
        const uint32_t st = smem_base + (uint32_t)s * STAGE_BYTES;
        const int koff = c * 32;
#pragma unroll
        for (int i = 0; i < 8; i++) {
            int idx  = i * 256 + tid;
            int comp = idx >> 9;
            int rem  = idx & 511;
            int row  = rem >> 2;
            int seg  = rem & 3;
            uint32_t dst = st + (uint32_t)comp * COMP_BYTES
                         + (uint32_t)row * ROW_PITCH + (uint32_t)seg * 16;
            const __nv_bfloat16* src;
            size_t roff;
            if (comp <= 1) {
                int gr = m0 + row;
                if (row_idx) gr = __ldg(&row_idx[gr]);
                src = (comp == 0) ? Ahi : Alo;
                roff = (size_t)gr * K;
            } else if (comp == 2) { src = Whi; roff = (size_t)(n0 + row) * K; }
            else                  { src = Wlo; roff = (size_t)(n0 + row) * K; }
            cpasync16(dst, src + roff + koff + seg * 8);
        }
        asm volatile("cp.async.commit_group;" ::: "memory");
    };

    float acc[4][4][4];
#pragma unroll
    for (int i = 0; i < 4; i++)
#pragma unroll
        for (int j = 0; j < 4; j++)
#pragma unroll
            for (int r = 0; r < 4; r++) acc[i][j][r] = 0.f;

    load_chunk(0, 0);

    for (int c = 0; c < nk; c++) {
        if (c + 1 < nk) {
            load_chunk(c + 1, (c + 1) & 1);
            asm volatile("cp.async.wait_group 1;" ::: "memory");
        } else {
            asm volatile("cp.async.wait_group 0;" ::: "memory");
        }
        __syncthreads();

        const uint32_t sb = smem_base + (uint32_t)(c & 1) * STAGE_BYTES;
        const uint32_t aBase = sb + (uint32_t)(warpM * 64) * ROW_PITCH;
        const uint32_t bBase = sb + 2u * COMP_BYTES + (uint32_t)(warpN * 32) * ROW_PITCH;

#pragma unroll
        for (int t = 0; t < 2; t++) {
            const uint32_t kb = (uint32_t)t * 32;

            uint32_t bh[4][2], bl[4][2];
#pragma unroll
            for (int jj = 0; jj < 2; jj++) {
                uint32_t r4[4];
                uint32_t addr = bBase + (uint32_t)(jj * 16) * ROW_PITCH + kb + b_lrow;
                ldsm_x4(r4, addr);
                bh[jj * 2][0] = r4[0]; bh[jj * 2][1] = r4[1];
                bh[jj * 2 + 1][0] = r4[2]; bh[jj * 2 + 1][1] = r4[3];
                ldsm_x4(r4, addr + COMP_BYTES);
                bl[jj * 2][0] = r4[0]; bl[jj * 2][1] = r4[1];
                bl[jj * 2 + 1][0] = r4[2]; bl[jj * 2 + 1][1] = r4[3];
            }
            uint32_t ah[4][4];
#pragma unroll
            for (int i = 0; i < 4; i++)
                ldsm_x4(ah[i], aBase + (uint32_t)(i * 16) * ROW_PITCH + kb + a_lrow);

#pragma unroll
            for (int i = 0; i < 4; i++)
#pragma unroll
                for (int j = 0; j < 4; j++) {
                    mma_bf16(acc[i][j], ah[i], bh[j]);
                    mma_bf16(acc[i][j], ah[i], bl[j]);
                }
            uint32_t al[4][4];
#pragma unroll
            for (int i = 0; i < 4; i++)
                ldsm_x4(al[i], aBase + COMP_BYTES + (uint32_t)(i * 16) * ROW_PITCH + kb + a_lrow);
#pragma unroll
            for (int i = 0; i < 4; i++)
#pragma unroll
                for (int j = 0; j < 4; j++)
                    mma_bf16(acc[i][j], al[i], bh[j]);
        }
        __syncthreads();
    }

    // ---- epilogue ----------------------------------------------------------
#pragma unroll
    for (int j = 0; j < 4; j++) {
        const int cc = n0 + warpN * 32 + j * 8 + tk * 2;
        const float b0v = bias[cc];
        const float b1v = bias[cc + 1];
#pragma unroll
        for (int i = 0; i < 4; i++) {
            const int r0 = m0 + warpM * 64 + i * 16 + g;
#pragma unroll
            for (int half = 0; half < 2; half++) {
                const int r = r0 + half * 8;
                float v0 = acc[i][j][half * 2 + 0] + b0v;
                float v1 = acc[i][j][half * 2 + 1] + b1v;
                const size_t off = (size_t)r * Ntot + cc;
                if (write_raw)
                    *(float2*)(raw_out + off) = make_float2(v0, v1);
                v0 = fmaxf(v0, 0.f);
                v1 = fmaxf(v1, 0.f);
                __nv_bfloat16 h0, l0, h1, l1;
                split_bf16(v0, h0, l0);
                split_bf16(v1, h1, l1);
                uint32_t hp = (uint32_t)__bfloat16_as_ushort(h0)
                            | ((uint32_t)__bfloat16_as_ushort(h1) << 16);
                uint32_t lp = (uint32_t)__bfloat16_as_ushort(l0)
                            | ((uint32_t)__bfloat16_as_ushort(l1) << 16);
                *(uint32_t*)(Ohi + off) = hp;
                *(uint32_t*)(Olo + off) = lp;
            }
        }
    }
}

// ---- prep: relu + bf16 hi/lo split of x -------------------------------------
__global__ void prep_split_relu(const float* __restrict__ src,
                                __nv_bfloat16* __restrict__ hi,
                                __nv_bfloat16* __restrict__ lo, int n)
{
    int t = blockIdx.x * blockDim.x + threadIdx.x;
    if (t >= n) return;
    float v = fmaxf(src[t], 0.0f);
    __nv_bfloat16 h, l;
    split_bf16(v, h, l);
    hi[t] = h; lo[t] = l;
}

// ---- prep: ALL weights transpose+split in one launch ------------------------
__global__ void prep_all(const float* __restrict__ W0, const float* __restrict__ W1,
                         const float* __restrict__ W2, const float* __restrict__ SW0,
                         const float* __restrict__ SW1,
                         __nv_bfloat16* __restrict__ hi, __nv_bfloat16* __restrict__ lo)
{
    int t = blockIdx.x * blockDim.x + threadIdx.x;
    if (t >= 1736704) return;
    const float* src;
    int local, Kd, Nd;
    unsigned int dbase;
    if (t < 294912) {
        if (t < 32768) { src = W0; local = t; Kd = 64; Nd = 512; dbase = OFF_W0; }
        else           { src = W1; local = t - 32768; Kd = 512; Nd = 512; dbase = OFF_W1; }
    } else if (t < 557056) {
        src = W2; local = t - 294912; Kd = 512; Nd = 512; dbase = OFF_W2;
    } else if (t < 1343488) {
        int u = t - 557056;
        int p = u / 262144;
        local = u - p * 262144;
        src = SW0 + (size_t)p * 262144; Kd = 512; Nd = 512;
        dbase = OFF_SW0 + (unsigned int)p * 262144u;
    } else {
        int u = t - 1343488;
        int p = u / 131072;
        local = u - p * 131072;
        src = SW1 + (size_t)p * 131072; Kd = 512; Nd = 256;
        dbase = OFF_SW1 + (unsigned int)p * 131072u;
    }
    int k = local / Nd, n = local % Nd;
    float v = src[local];
    __nv_bfloat16 h, l;
    split_bf16(v, h, l);
    size_t d = (size_t)dbase + (size_t)n * Kd + k;
    hi[d] = h; lo[d] = l;
}

// ---- index build ------------------------------------------------------------
__global__ void idx_reset() {
    if (threadIdx.x < 4) { g_cnt[threadIdx.x] = 0; g_cntpad[threadIdx.x] = 0; }
}
__global__ void idx_build(const int* __restrict__ y, const int* __restrict__ pairs, int n)
{
    int t = blockIdx.x * blockDim.x + threadIdx.x;
    if (t >= n) return;
    int yv = y[t];
#pragma unroll
    for (int p = 0; p < 3; p++) {
        if (yv == pairs[2 * p] || yv == pairs[2 * p + 1]) {
            int pos = atomicAdd(&g_cnt[p], 1);
            g_idx[p * IDX_STRIDE + pos] = t;
        }
    }
}
__global__ void idx_pad()
{
    int p = blockIdx.x;
    int c = g_cnt[p];
    int cp = (c + 127) & ~127;
    for (int i = c + threadIdx.x; i < cp; i += 128)
        g_idx[p * IDX_STRIDE + i] = 0;
    if (threadIdx.x == 0) g_cntpad[p] = cp;
}

// ---- final (z-batched): packed rows, scatter to original index --------------
__global__ void subnet_final(const __nv_bfloat16* __restrict__ s1h_base,
                             const __nv_bfloat16* __restrict__ s1l_base,
                             const float* __restrict__ SW2,
                             const float* __restrict__ Sb2,
                             const int*   __restrict__ idx_base,
                             const int*   __restrict__ cnt_base,
                             float* __restrict__ out_r,
                             float* __restrict__ out_s,
                             float* __restrict__ out_m)
{
    const int p = blockIdx.z;
    const __nv_bfloat16* s1h = s1h_base + (size_t)p * GN * 256;
    const __nv_bfloat16* s1l = s1l_base + (size_t)p * GN * 256;
    const int* idxlist = idx_base + (size_t)p * IDX_STRIDE;
    float* r_out = out_r + (size_t)p * GN;
    float* s_out = out_s + (size_t)p * GN;
    float* m_out = out_m + (size_t)p * GN;

    __shared__ float w[256];
    const int tid = threadIdx.x;
    w[tid] = SW2[p * 256 + tid];
    __syncthreads();

    const float sb = Sb2[p];
    const int limit = __ldg(cnt_base + p);

    const int lane = tid & 31;
    const int warp = tid >> 5;
    const int gw = blockIdx.x * (blockDim.x >> 5) + warp;
    const int warps_total = gridDim.x * (blockDim.x >> 5);

    for (int n = gw; n < limit; n += warps_total) {
        const size_t base = (size_t)n * 256;
        float acc = 0.f;
#pragma unroll
        for (int j = 0; j < 8; j++) {
            int c = lane + 32 * j;
            float v = __bfloat162float(s1h[base + c]) + __bfloat162float(s1l[base + c]);
            acc += v * w[c];
        }
#pragma unroll
        for (int o = 16; o > 0; o >>= 1)
            acc += __shfl_xor_sync(0xFFFFFFFFu, acc, o);

        if (lane == 0) {
            float logit = acc + sb;
            float s = 1.f / (1.f + expf(-logit));
            s = fmaxf(s, 1e-9f);
            float r = (1.f - s) / s;
            int orig = __ldg(&idxlist[n]);
            r_out[orig] = r;
            s_out[orig] = s;
            m_out[orig] = 1.f;
        }
    }
}

// ============================================================================
extern "C" void kernel_launch(void* const* d_in, const int* in_sizes, int n_in,
                              void* d_out, int out_size)
{
    const float* x     = (const float*)d_in[0];
    const int*   y     = (const int*)  d_in[1];
    const int*   pairs = (const int*)  d_in[2];
    const float* W0    = (const float*)d_in[3];
    const float* b0    = (const float*)d_in[4];
    const float* W1    = (const float*)d_in[5];
    const float* b1    = (const float*)d_in[6];
    const float* W2    = (const float*)d_in[7];
    const float* b2    = (const float*)d_in[8];
    const float* SW0   = (const float*)d_in[9];
    const float* Sb0   = (const float*)d_in[10];
    const float* SW1   = (const float*)d_in[11];
    const float* Sb1   = (const float*)d_in[12];
    const float* SW2   = (const float*)d_in[13];
    const float* Sb2   = (const float*)d_in[14];

    const int M = GN;
    float* out   = (float*)d_out;
    float* repr  = out;
    float* r_seg = out + (size_t)M * 512;
    float* s_seg = r_seg + 3 * (size_t)M;
    float* m_seg = s_seg + 3 * (size_t)M;

    __nv_bfloat16 *hiA, *loA, *hiB, *loB, *hiC, *loC, *hiX, *loX, *whi, *wlo;
    cudaGetSymbolAddress((void**)&hiA, g_hiA);
    cudaGetSymbolAddress((void**)&loA, g_loA);
    cudaGetSymbolAddress((void**)&hiB, g_hiB);
    cudaGetSymbolAddress((void**)&loB, g_loB);
    cudaGetSymbolAddress((void**)&hiC, g_hiC);
    cudaGetSymbolAddress((void**)&loC, g_loC);
    cudaGetSymbolAddress((void**)&hiX, g_hiX);
    cudaGetSymbolAddress((void**)&loX, g_loX);
    cudaGetSymbolAddress((void**)&whi, g_whi);
    cudaGetSymbolAddress((void**)&wlo, g_wlo);
    int *idxp, *cntp, *cntpadp;
    cudaGetSymbolAddress((void**)&idxp, g_idx);
    cudaGetSymbolAddress((void**)&cntp, g_cnt);
    cudaGetSymbolAddress((void**)&cntpadp, g_cntpad);

    cudaFuncSetAttribute(gemm_mma, cudaFuncAttributeMaxDynamicSharedMemorySize,
                         2 * STAGE_BYTES);

    cudaMemsetAsync(r_seg, 0, 9 * (size_t)M * sizeof(float));

    prep_split_relu<<<(M * 64 + 255) / 256, 256>>>(x, hiX, loX, M * 64);
    prep_all<<<(1736704 + 255) / 256, 256>>>(W0, W1, W2, SW0, SW1, whi, wlo);
    idx_reset<<<1, 32>>>();
    idx_build<<<(M + 255) / 256, 256>>>(y, pairs, M);
    idx_pad<<<3, 128>>>();

    dim3 blk(256);
    const size_t shmem = 2 * STAGE_BYTES;

    // trunk (dense, z=1, strides 0)
    gemm_mma<<<dim3(4, M / 128, 1), blk, shmem>>>(
        hiX, loX, 0, whi + OFF_W0, wlo + OFF_W0, 0, b0, 0,
        nullptr, hiA, loA, 0, 64, 512, 0, nullptr, nullptr);
    gemm_mma<<<dim3(4, M / 128, 1), blk, shmem>>>(
        hiA, loA, 0, whi + OFF_W1, wlo + OFF_W1, 0, b1, 0,
        nullptr, hiB, loB, 0, 512, 512, 0, nullptr, nullptr);
    gemm_mma<<<dim3(4, M / 128, 1), blk, shmem>>>(
        hiB, loB, 0, whi + OFF_W2, wlo + OFF_W2, 0, b2, 0,
        repr, hiA, loA, 0, 512, 512, 1, nullptr, nullptr);

    // SW0: all 3 pairs in one launch (gathered rows, packed outputs)
    gemm_mma<<<dim3(4, M / 128, 3), blk, shmem>>>(
        hiA, loA, 0,
        whi + OFF_SW0, wlo + OFF_SW0, 262144,
        Sb0, 512,
        nullptr, hiB, loB, (size_t)GN * 512,
        512, 512, 0, idxp, cntpadp);

    // SW1: all 3 pairs in one launch (dense on packed rows)
    gemm_mma<<<dim3(2, M / 128, 3), blk, shmem>>>(
        hiB, loB, (size_t)GN * 512,
        whi + OFF_SW1, wlo + OFF_SW1, 131072,
        Sb1, 256,
        nullptr, hiC, loC, (size_t)GN * 256,
        512, 256, 0, nullptr, cntpadp);

    // final: all 3 pairs in one launch
    subnet_final<<<dim3(512, 1, 3), dim3(256)>>>(
        hiC, loC, SW2, Sb2, idxp, cntp, r_seg, s_seg, m_seg);
}

// round 11
// speedup vs baseline: 1.9396x; 1.2461x over previous
#include <cuda_runtime.h>
#include <cuda_bf16.h>
#include <cuda_fp16.h>
#include <cstdint>
#include <math.h>

// ============================================================================
// EnsembleRatioModel — round 10: mixed precision terms.
//   Trunk:  3-term bf16 split (A_hi.W_hi + A_hi.W_lo + A_lo.W_hi)  — repr_ exact-ish
//   Subnet: 2-term fp16       (A_h16 . (W_hi + W_lo))              — 33% less work
// Row compaction + z-batched subnet launches retained from R8/R9.
//
// Output packing (validated): [N*512) repr_ ; [3N) r*m ; [3N) s*m ; [3N) m
// ============================================================================

#define GN 131072

__device__ unsigned short g_hiA[GN * 512];            // trunk act hi / fp16 repr act
__device__ unsigned short g_loA[GN * 512];
__device__ unsigned short g_hiB[3ULL * GN * 512];     // trunk L2 out (slice 0) + SW0 outs
__device__ unsigned short g_loB[GN * 512];            // trunk L2 lo only
__device__ float          g_fC[3ULL * GN * 256];      // SW1 raw fp32 outs
__device__ unsigned short g_hiX[GN * 64];
__device__ unsigned short g_loX[GN * 64];
__device__ unsigned short g_whi[1736704];
__device__ unsigned short g_wlo[1736704];

__device__ int g_cnt[4];
__device__ int g_cntpad[4];
__device__ int g_idx[3 * (GN + 128)];

#define IDX_STRIDE (GN + 128)

#define OFF_W0   0u
#define OFF_W1   32768u
#define OFF_W2   294912u
#define OFF_SW0  557056u      /* + p*262144 */
#define OFF_SW1  1343488u     /* + p*131072 */

// ---------------- helpers ----------------------------------------------------
__device__ __forceinline__ uint32_t smem_u32(const void* p) {
    uint32_t a;
    asm("{ .reg .u64 t; cvta.to.shared.u64 t, %1; cvt.u32.u64 %0, t; }"
        : "=r"(a) : "l"(p));
    return a;
}
__device__ __forceinline__ void cpasync16(uint32_t dst, const void* src) {
    asm volatile("cp.async.cg.shared.global [%0], [%1], 16;"
                 :: "r"(dst), "l"(src) : "memory");
}
__device__ __forceinline__ void ldsm_x4(uint32_t* r, uint32_t addr) {
    asm volatile("ldmatrix.sync.aligned.m8n8.x4.shared.b16 {%0,%1,%2,%3}, [%4];"
                 : "=r"(r[0]), "=r"(r[1]), "=r"(r[2]), "=r"(r[3]) : "r"(addr));
}
__device__ __forceinline__ void mma_bf16(float* d, const uint32_t* a,
                                         const uint32_t* b) {
    asm volatile(
        "mma.sync.aligned.m16n8k16.row.col.f32.bf16.bf16.f32 "
        "{%0,%1,%2,%3}, {%4,%5,%6,%7}, {%8,%9}, {%0,%1,%2,%3};"
        : "+f"(d[0]), "+f"(d[1]), "+f"(d[2]), "+f"(d[3])
        : "r"(a[0]), "r"(a[1]), "r"(a[2]), "r"(a[3]), "r"(b[0]), "r"(b[1]));
}
__device__ __forceinline__ void mma_f16(float* d, const uint32_t* a,
                                        const uint32_t* b) {
    asm volatile(
        "mma.sync.aligned.m16n8k16.row.col.f32.f16.f16.f32 "
        "{%0,%1,%2,%3}, {%4,%5,%6,%7}, {%8,%9}, {%0,%1,%2,%3};"
        : "+f"(d[0]), "+f"(d[1]), "+f"(d[2]), "+f"(d[3])
        : "r"(a[0]), "r"(a[1]), "r"(a[2]), "r"(a[3]), "r"(b[0]), "r"(b[1]));
}
__device__ __forceinline__ void split_bf16(float v, __nv_bfloat16& h, __nv_bfloat16& l) {
    h = __float2bfloat16(v);
    l = __float2bfloat16(v - __bfloat162float(h));
}
__device__ __forceinline__ void split_fp16(float v, __half& h, __half& l) {
    h = __float2half_rn(v);
    l = __float2half_rn(v - __half2float(h));
}

// ============================================================================
// GEMM template. CMODE: 0 = bf16 3-term (A hi+lo, W hi+lo), 1 = fp16 2-term
// (A single, W hi+lo). OMODE: 0 = bf16 hi/lo pair out; 1 = fp16 single out
// (+opt fp32 raw); 2 = fp32 raw out only.
// 128x128 CTA tile, 256 thr, warp 64x32, K-chunk 32, double buffer.
// ============================================================================
#define STAGE_BYTES 40960
#define COMP_BYTES  10240
#define ROW_PITCH   80

template<int CMODE, int OMODE>
__global__ void __launch_bounds__(256, 2)
gemm_mma(const unsigned short* __restrict__ Ahi, const unsigned short* __restrict__ Alo,
         size_t a_ps,
         const unsigned short* __restrict__ Whi, const unsigned short* __restrict__ Wlo,
         size_t w_ps,
         const float* __restrict__ bias, size_t b_ps,
         float* __restrict__ raw_out, size_t r_ps,
         unsigned short* __restrict__ Ohi, unsigned short* __restrict__ Olo,
         size_t o_ps,
         int K, int Ntot, int write_raw,
         const int* __restrict__ row_idx_base, const int* __restrict__ cnt_base)
{
    extern __shared__ __align__(16) char smem[];
    const uint32_t smem_base = smem_u32(smem);

    const int p  = blockIdx.z;
    const int m0 = blockIdx.y * 128;
    if (cnt_base && m0 >= __ldg(cnt_base + p)) return;
    const int n0 = blockIdx.x * 128;

    const int* row_idx = row_idx_base ? row_idx_base + (size_t)p * IDX_STRIDE : nullptr;
    Ahi += (size_t)p * a_ps;  Alo += (size_t)p * a_ps;
    Whi += (size_t)p * w_ps;  Wlo += (size_t)p * w_ps;
    bias += (size_t)p * b_ps;
    raw_out += (size_t)p * r_ps;
    Ohi += (size_t)p * o_ps;  Olo += (size_t)p * o_ps;

    const int tid   = threadIdx.x;
    const int wid   = tid >> 5;
    const int lane  = tid & 31;
    const int g     = lane >> 2;
    const int tk    = lane & 3;
    const int warpM = wid >> 2;
    const int warpN = wid & 3;

    const int nk = K >> 5;

    const uint32_t a_lrow = (uint32_t)(lane & 15) * ROW_PITCH + (uint32_t)(lane >> 4) * 16;
    const uint32_t b_lrow = (uint32_t)((lane & 7) + ((lane >> 4) << 3)) * ROW_PITCH
                          + (uint32_t)((lane >> 3) & 1) * 16;

    auto load_chunk = [&](int c, int s) {
        const uint32_t st = smem_base + (uint32_t)s * STAGE_BYTES;
        const int koff = c * 32;
#pragma unroll
        for (int i = 0; i < 8; i++) {
            int idx  = i * 256 + tid;
            int comp = idx >> 9;
            if (CMODE == 1 && comp == 1) continue;   // no A-lo in 2-term mode
            int rem  = idx & 511;
            int row  = rem >> 2;
            int seg  = rem & 3;
            uint32_t dst = st + (uint32_t)comp * COMP_BYTES
                         + (uint32_t)row * ROW_PITCH + (uint32_t)seg * 16;
            const unsigned short* src;
            size_t roff;
            if (comp <= 1) {
                int gr = m0 + row;
                if (row_idx) gr = __ldg(&row_idx[gr]);
                src = (comp == 0) ? Ahi : Alo;
                roff = (size_t)gr * K;
            } else if (comp == 2) { src = Whi; roff = (size_t)(n0 + row) * K; }
            else                  { src = Wlo; roff = (size_t)(n0 + row) * K; }
            cpasync16(dst, src + roff + koff + seg * 8);
        }
        asm volatile("cp.async.commit_group;" ::: "memory");
    };

    float acc[4][4][4];
#pragma unroll
    for (int i = 0; i < 4; i++)
#pragma unroll
        for (int j = 0; j < 4; j++)
#pragma unroll
            for (int r = 0; r < 4; r++) acc[i][j][r] = 0.f;

    load_chunk(0, 0);

    for (int c = 0; c < nk; c++) {
        if (c + 1 < nk) {
            load_chunk(c + 1, (c + 1) & 1);
            asm volatile("cp.async.wait_group 1;" ::: "memory");
        } else {
            asm volatile("cp.async.wait_group 0;" ::: "memory");
        }
        __syncthreads();

        const uint32_t sb = smem_base + (uint32_t)(c & 1) * STAGE_BYTES;
        const uint32_t aBase = sb + (uint32_t)(warpM * 64) * ROW_PITCH;
        const uint32_t bBase = sb + 2u * COMP_BYTES + (uint32_t)(warpN * 32) * ROW_PITCH;

#pragma unroll
        for (int t = 0; t < 2; t++) {
            const uint32_t kb = (uint32_t)t * 32;

            uint32_t bh[4][2], bl[4][2];
#pragma unroll
            for (int jj = 0; jj < 2; jj++) {
                uint32_t r4[4];
                uint32_t addr = bBase + (uint32_t)(jj * 16) * ROW_PITCH + kb + b_lrow;
                ldsm_x4(r4, addr);
                bh[jj * 2][0] = r4[0]; bh[jj * 2][1] = r4[1];
                bh[jj * 2 + 1][0] = r4[2]; bh[jj * 2 + 1][1] = r4[3];
                ldsm_x4(r4, addr + COMP_BYTES);
                bl[jj * 2][0] = r4[0]; bl[jj * 2][1] = r4[1];
                bl[jj * 2 + 1][0] = r4[2]; bl[jj * 2 + 1][1] = r4[3];
            }
            uint32_t ah[4][4];
#pragma unroll
            for (int i = 0; i < 4; i++)
                ldsm_x4(ah[i], aBase + (uint32_t)(i * 16) * ROW_PITCH + kb + a_lrow);

            if (CMODE == 0) {
#pragma unroll
                for (int i = 0; i < 4; i++)
#pragma unroll
                    for (int j = 0; j < 4; j++) {
                        mma_bf16(acc[i][j], ah[i], bh[j]);
                        mma_bf16(acc[i][j], ah[i], bl[j]);
                    }
                uint32_t al[4][4];
#pragma unroll
                for (int i = 0; i < 4; i++)
                    ldsm_x4(al[i], aBase + COMP_BYTES + (uint32_t)(i * 16) * ROW_PITCH + kb + a_lrow);
#pragma unroll
                for (int i = 0; i < 4; i++)
#pragma unroll
                    for (int j = 0; j < 4; j++)
                        mma_bf16(acc[i][j], al[i], bh[j]);
            } else {
#pragma unroll
                for (int i = 0; i < 4; i++)
#pragma unroll
                    for (int j = 0; j < 4; j++) {
                        mma_f16(acc[i][j], ah[i], bh[j]);
                        mma_f16(acc[i][j], ah[i], bl[j]);
                    }
            }
        }
        __syncthreads();
    }

    // ---- epilogue ----------------------------------------------------------
#pragma unroll
    for (int j = 0; j < 4; j++) {
        const int cc = n0 + warpN * 32 + j * 8 + tk * 2;
        const float b0v = bias[cc];
        const float b1v = bias[cc + 1];
#pragma unroll
        for (int i = 0; i < 4; i++) {
            const int r0 = m0 + warpM * 64 + i * 16 + g;
#pragma unroll
            for (int half = 0; half < 2; half++) {
                const int r = r0 + half * 8;
                float v0 = acc[i][j][half * 2 + 0] + b0v;
                float v1 = acc[i][j][half * 2 + 1] + b1v;
                const size_t off = (size_t)r * Ntot + cc;
                if (OMODE == 2) {
                    *(float2*)(raw_out + off) = make_float2(v0, v1);
                } else {
                    if (write_raw)
                        *(float2*)(raw_out + off) = make_float2(v0, v1);
                    float rv0 = fmaxf(v0, 0.f);
                    float rv1 = fmaxf(v1, 0.f);
                    if (OMODE == 0) {
                        __nv_bfloat16 h0, l0, h1, l1;
                        split_bf16(rv0, h0, l0);
                        split_bf16(rv1, h1, l1);
                        uint32_t hp = (uint32_t)__bfloat16_as_ushort(h0)
                                    | ((uint32_t)__bfloat16_as_ushort(h1) << 16);
                        uint32_t lp = (uint32_t)__bfloat16_as_ushort(l0)
                                    | ((uint32_t)__bfloat16_as_ushort(l1) << 16);
                        *(uint32_t*)(Ohi + off) = hp;
                        *(uint32_t*)(Olo + off) = lp;
                    } else {  // OMODE == 1: fp16 single
                        __half h0 = __float2half_rn(rv0);
                        __half h1 = __float2half_rn(rv1);
                        uint32_t hp = (uint32_t)__half_as_ushort(h0)
                                    | ((uint32_t)__half_as_ushort(h1) << 16);
                        *(uint32_t*)(Ohi + off) = hp;
                    }
                }
            }
        }
    }
}

// ---- prep: relu + bf16 hi/lo split of x -------------------------------------
__global__ void prep_split_relu(const float* __restrict__ src,
                                unsigned short* __restrict__ hi,
                                unsigned short* __restrict__ lo, int n)
{
    int t = blockIdx.x * blockDim.x + threadIdx.x;
    if (t >= n) return;
    float v = fmaxf(src[t], 0.0f);
    __nv_bfloat16 h, l;
    split_bf16(v, h, l);
    hi[t] = __bfloat16_as_ushort(h);
    lo[t] = __bfloat16_as_ushort(l);
}

// ---- prep: ALL weights transpose+split (trunk bf16, subnets fp16) -----------
__global__ void prep_all(const float* __restrict__ W0, const float* __restrict__ W1,
                         const float* __restrict__ W2, const float* __restrict__ SW0,
                         const float* __restrict__ SW1,
                         unsigned short* __restrict__ hi, unsigned short* __restrict__ lo)
{
    int t = blockIdx.x * blockDim.x + threadIdx.x;
    if (t >= 1736704) return;
    const float* src;
    int local, Kd, Nd;
    unsigned int dbase;
    bool f16 = false;
    if (t < 294912) {
        if (t < 32768) { src = W0; local = t; Kd = 64; Nd = 512; dbase = OFF_W0; }
        else           { src = W1; local = t - 32768; Kd = 512; Nd = 512; dbase = OFF_W1; }
    } else if (t < 557056) {
        src = W2; local = t - 294912; Kd = 512; Nd = 512; dbase = OFF_W2;
    } else if (t < 1343488) {
        int u = t - 557056;
        int p = u / 262144;
        local = u - p * 262144;
        src = SW0 + (size_t)p * 262144; Kd = 512; Nd = 512;
        dbase = OFF_SW0 + (unsigned int)p * 262144u;
        f16 = true;
    } else {
        int u = t - 1343488;
        int p = u / 131072;
        local = u - p * 131072;
        src = SW1 + (size_t)p * 131072; Kd = 512; Nd = 256;
        dbase = OFF_SW1 + (unsigned int)p * 131072u;
        f16 = true;
    }
    int k = local / Nd, n = local % Nd;
    float v = src[local];
    size_t d = (size_t)dbase + (size_t)n * Kd + k;
    if (f16) {
        __half h, l;
        split_fp16(v, h, l);
        hi[d] = __half_as_ushort(h);
        lo[d] = __half_as_ushort(l);
    } else {
        __nv_bfloat16 h, l;
        split_bf16(v, h, l);
        hi[d] = __bfloat16_as_ushort(h);
        lo[d] = __bfloat16_as_ushort(l);
    }
}

// ---- index build ------------------------------------------------------------
__global__ void idx_reset() {
    if (threadIdx.x < 4) { g_cnt[threadIdx.x] = 0; g_cntpad[threadIdx.x] = 0; }
}
__global__ void idx_build(const int* __restrict__ y, const int* __restrict__ pairs, int n)
{
    int t = blockIdx.x * blockDim.x + threadIdx.x;
    if (t >= n) return;
    int yv = y[t];
#pragma unroll
    for (int p = 0; p < 3; p++) {
        if (yv == pairs[2 * p] || yv == pairs[2 * p + 1]) {
            int pos = atomicAdd(&g_cnt[p], 1);
            g_idx[p * IDX_STRIDE + pos] = t;
        }
    }
}
__global__ void idx_pad()
{
    int p = blockIdx.x;
    int c = g_cnt[p];
    int cp = (c + 127) & ~127;
    for (int i = c + threadIdx.x; i < cp; i += 128)
        g_idx[p * IDX_STRIDE + i] = 0;
    if (threadIdx.x == 0) g_cntpad[p] = cp;
}

// ---- final (z-batched): fp32 packed rows, scatter to original index ---------
__global__ void subnet_final(const float* __restrict__ fC_base,
                             const float* __restrict__ SW2,
                             const float* __restrict__ Sb2,
                             const int*   __restrict__ idx_base,
                             const int*   __restrict__ cnt_base,
                             float* __restrict__ out_r,
                             float* __restrict__ out_s,
                             float* __restrict__ out_m)
{
    const int p = blockIdx.z;
    const float* fC = fC_base + (size_t)p * GN * 256;
    const int* idxlist = idx_base + (size_t)p * IDX_STRIDE;
    float* r_out = out_r + (size_t)p * GN;
    float* s_out = out_s + (size_t)p * GN;
    float* m_out = out_m + (size_t)p * GN;

    __shared__ float w[256];
    const int tid = threadIdx.x;
    w[tid] = SW2[p * 256 + tid];
    __syncthreads();

    const float sb = Sb2[p];
    const int limit = __ldg(cnt_base + p);

    const int lane = tid & 31;
    const int warp = tid >> 5;
    const int gw = blockIdx.x * (blockDim.x >> 5) + warp;
    const int warps_total = gridDim.x * (blockDim.x >> 5);

    for (int n = gw; n < limit; n += warps_total) {
        const size_t base = (size_t)n * 256;
        float acc = 0.f;
#pragma unroll
        for (int j = 0; j < 8; j++) {
            int c = lane + 32 * j;
            acc += fmaxf(fC[base + c], 0.f) * w[c];
        }
#pragma unroll
        for (int o = 16; o > 0; o >>= 1)
            acc += __shfl_xor_sync(0xFFFFFFFFu, acc, o);

        if (lane == 0) {
            float logit = acc + sb;
            float s = 1.f / (1.f + expf(-logit));
            s = fmaxf(s, 1e-9f);
            float r = (1.f - s) / s;
            int orig = __ldg(&idxlist[n]);
            r_out[orig] = r;
            s_out[orig] = s;
            m_out[orig] = 1.f;
        }
    }
}

// ============================================================================
extern "C" void kernel_launch(void* const* d_in, const int* in_sizes, int n_in,
                              void* d_out, int out_size)
{
    const float* x     = (const float*)d_in[0];
    const int*   y     = (const int*)  d_in[1];
    const int*   pairs = (const int*)  d_in[2];
    const float* W0    = (const float*)d_in[3];
    const float* b0    = (const float*)d_in[4];
    const float* W1    = (const float*)d_in[5];
    const float* b1    = (const float*)d_in[6];
    const float* W2    = (const float*)d_in[7];
    const float* b2    = (const float*)d_in[8];
    const float* SW0   = (const float*)d_in[9];
    const float* Sb0   = (const float*)d_in[10];
    const float* SW1   = (const float*)d_in[11];
    const float* Sb1   = (const float*)d_in[12];
    const float* SW2   = (const float*)d_in[13];
    const float* Sb2   = (const float*)d_in[14];

    const int M = GN;
    float* out   = (float*)d_out;
    float* repr  = out;
    float* r_seg = out + (size_t)M * 512;
    float* s_seg = r_seg + 3 * (size_t)M;
    float* m_seg = s_seg + 3 * (size_t)M;

    unsigned short *hiA, *loA, *hiB, *loB, *hiX, *loX, *whi, *wlo;
    float *fC;
    cudaGetSymbolAddress((void**)&hiA, g_hiA);
    cudaGetSymbolAddress((void**)&loA, g_loA);
    cudaGetSymbolAddress((void**)&hiB, g_hiB);
    cudaGetSymbolAddress((void**)&loB, g_loB);
    cudaGetSymbolAddress((void**)&fC,  g_fC);
    cudaGetSymbolAddress((void**)&hiX, g_hiX);
    cudaGetSymbolAddress((void**)&loX, g_loX);
    cudaGetSymbolAddress((void**)&whi, g_whi);
    cudaGetSymbolAddress((void**)&wlo, g_wlo);
    int *idxp, *cntp, *cntpadp;
    cudaGetSymbolAddress((void**)&idxp, g_idx);
    cudaGetSymbolAddress((void**)&cntp, g_cnt);
    cudaGetSymbolAddress((void**)&cntpadp, g_cntpad);

    cudaFuncSetAttribute((const void*)gemm_mma<0,0>,
        cudaFuncAttributeMaxDynamicSharedMemorySize, 2 * STAGE_BYTES);
    cudaFuncSetAttribute((const void*)gemm_mma<0,1>,
        cudaFuncAttributeMaxDynamicSharedMemorySize, 2 * STAGE_BYTES);
    cudaFuncSetAttribute((const void*)gemm_mma<1,1>,
        cudaFuncAttributeMaxDynamicSharedMemorySize, 2 * STAGE_BYTES);
    cudaFuncSetAttribute((const void*)gemm_mma<1,2>,
        cudaFuncAttributeMaxDynamicSharedMemorySize, 2 * STAGE_BYTES);

    cudaMemsetAsync(r_seg, 0, 9 * (size_t)M * sizeof(float));

    prep_split_relu<<<(M * 64 + 255) / 256, 256>>>(x, hiX, loX, M * 64);
    prep_all<<<(1736704 + 255) / 256, 256>>>(W0, W1, W2, SW0, SW1, whi, wlo);
    idx_reset<<<1, 32>>>();
    idx_build<<<(M + 255) / 256, 256>>>(y, pairs, M);
    idx_pad<<<3, 128>>>();

    dim3 blk(256);
    const size_t shmem = 2 * STAGE_BYTES;

    // trunk L1, L2: 3-term bf16, bf16-pair outputs
    gemm_mma<0,0><<<dim3(4, M / 128, 1), blk, shmem>>>(
        hiX, loX, 0, whi + OFF_W0, wlo + OFF_W0, 0, b0, 0,
        nullptr, 0, hiA, loA, 0, 64, 512, 0, nullptr, nullptr);
    gemm_mma<0,0><<<dim3(4, M / 128, 1), blk, shmem>>>(
        hiA, loA, 0, whi + OFF_W1, wlo + OFF_W1, 0, b1, 0,
        nullptr, 0, hiB, loB, 0, 512, 512, 0, nullptr, nullptr);
    // trunk L3: 3-term bf16, fp32 repr raw + fp16-single activation for SW0
    gemm_mma<0,1><<<dim3(4, M / 128, 1), blk, shmem>>>(
        hiB, loB, 0, whi + OFF_W2, wlo + OFF_W2, 0, b2, 0,
        repr, 0, hiA, nullptr, 0, 512, 512, 1, nullptr, nullptr);

    // SW0: 2-term fp16, z-batched, gathered rows, fp16-single outputs
    gemm_mma<1,1><<<dim3(4, M / 128, 3), blk, shmem>>>(
        hiA, hiA, 0,
        whi + OFF_SW0, wlo + OFF_SW0, 262144,
        Sb0, 512,
        nullptr, 0, hiB, nullptr, (size_t)GN * 512,
        512, 512, 0, idxp, cntpadp);

    // SW1: 2-term fp16, z-batched, fp32 raw outputs
    gemm_mma<1,2><<<dim3(2, M / 128, 3), blk, shmem>>>(
        hiB, hiB, (size_t)GN * 512,
        whi + OFF_SW1, wlo + OFF_SW1, 131072,
        Sb1, 256,
        fC, (size_t)GN * 256, nullptr, nullptr, 0,
        512, 256, 0, nullptr, cntpadp);

    // final
    subnet_final<<<dim3(512, 1, 3), dim3(256)>>>(
        fC, SW2, Sb2, idxp, cntp, r_seg, s_seg, m_seg);
}

// round 12
// speedup vs baseline: 2.8332x; 1.4607x over previous
#include <cuda_runtime.h>
#include <cuda_bf16.h>
#include <cuda_fp16.h>
#include <cstdint>
#include <math.h>

// ============================================================================
// EnsembleRatioModel — round 11: all-fp16 terms, calibrated to the error budget.
//   Trunk:  2-term fp16 (A_f16 . (W_hi + W_lo))  — repr_ local err ~4e-5
//   Subnet: 1-term fp16 (A_f16 .  W_f16)         — subnet local err ~4e-4
// Row compaction + z-batched subnet launches retained.
//
// Output packing (validated): [N*512) repr_ ; [3N) r*m ; [3N) s*m ; [3N) m
// ============================================================================

#define GN 131072

__device__ unsigned short g_X16[GN * 64];             // fp16 relu(x)
__device__ unsigned short g_A[GN * 512];              // fp16 trunk act ping
__device__ unsigned short g_B[3ULL * GN * 512];       // trunk pong (slice 0) + SW0 outs
__device__ float          g_fC[3ULL * GN * 256];      // SW1 raw fp32 outs
__device__ unsigned short g_whi[1736704];             // all weights, fp16 hi
__device__ unsigned short g_wlo[557056];              // trunk weights fp16 lo only

__device__ int g_cnt[4];
__device__ int g_cntpad[4];
__device__ int g_idx[3 * (GN + 128)];

#define IDX_STRIDE (GN + 128)

#define OFF_W0   0u
#define OFF_W1   32768u
#define OFF_W2   294912u
#define OFF_SW0  557056u      /* + p*262144 */
#define OFF_SW1  1343488u     /* + p*131072 */

// ---------------- helpers ----------------------------------------------------
__device__ __forceinline__ uint32_t smem_u32(const void* p) {
    uint32_t a;
    asm("{ .reg .u64 t; cvta.to.shared.u64 t, %1; cvt.u32.u64 %0, t; }"
        : "=r"(a) : "l"(p));
    return a;
}
__device__ __forceinline__ void cpasync16(uint32_t dst, const void* src) {
    asm volatile("cp.async.cg.shared.global [%0], [%1], 16;"
                 :: "r"(dst), "l"(src) : "memory");
}
__device__ __forceinline__ void ldsm_x4(uint32_t* r, uint32_t addr) {
    asm volatile("ldmatrix.sync.aligned.m8n8.x4.shared.b16 {%0,%1,%2,%3}, [%4];"
                 : "=r"(r[0]), "=r"(r[1]), "=r"(r[2]), "=r"(r[3]) : "r"(addr));
}
__device__ __forceinline__ void mma_f16(float* d, const uint32_t* a,
                                        const uint32_t* b) {
    asm volatile(
        "mma.sync.aligned.m16n8k16.row.col.f32.f16.f16.f32 "
        "{%0,%1,%2,%3}, {%4,%5,%6,%7}, {%8,%9}, {%0,%1,%2,%3};"
        : "+f"(d[0]), "+f"(d[1]), "+f"(d[2]), "+f"(d[3])
        : "r"(a[0]), "r"(a[1]), "r"(a[2]), "r"(a[3]), "r"(b[0]), "r"(b[1]));
}
__device__ __forceinline__ void split_fp16(float v, __half& h, __half& l) {
    h = __float2half_rn(v);
    l = __float2half_rn(v - __half2float(h));
}

// ============================================================================
// GEMM template. TERMS: 2 = A.(Whi+Wlo), 1 = A.Whi only.
// OMODE: 1 = fp16 single out (+opt fp32 raw); 2 = fp32 raw out only.
// 128x128 CTA tile, 256 thr, warp 64x32, K-chunk 32, double buffer.
// SMEM per stage: comps {A, -, Whi, Wlo} x 128 rows x 80B = 40960 B.
// ============================================================================
#define STAGE_BYTES 40960
#define COMP_BYTES  10240
#define ROW_PITCH   80

template<int TERMS, int OMODE>
__global__ void __launch_bounds__(256, 2)
gemm_mma(const unsigned short* __restrict__ A16, size_t a_ps,
         const unsigned short* __restrict__ Whi, const unsigned short* __restrict__ Wlo,
         size_t w_ps,
         const float* __restrict__ bias, size_t b_ps,
         float* __restrict__ raw_out, size_t r_ps,
         unsigned short* __restrict__ O16, size_t o_ps,
         int K, int Ntot, int write_raw,
         const int* __restrict__ row_idx_base, const int* __restrict__ cnt_base)
{
    extern __shared__ __align__(16) char smem[];
    const uint32_t smem_base = smem_u32(smem);

    const int p  = blockIdx.z;
    const int m0 = blockIdx.y * 128;
    if (cnt_base && m0 >= __ldg(cnt_base + p)) return;
    const int n0 = blockIdx.x * 128;

    const int* row_idx = row_idx_base ? row_idx_base + (size_t)p * IDX_STRIDE : nullptr;
    A16 += (size_t)p * a_ps;
    Whi += (size_t)p * w_ps;
    Wlo += (size_t)p * w_ps;
    bias += (size_t)p * b_ps;
    raw_out += (size_t)p * r_ps;
    O16 += (size_t)p * o_ps;

    const int tid   = threadIdx.x;
    const int wid   = tid >> 5;
    const int lane  = tid & 31;
    const int g     = lane >> 2;
    const int tk    = lane & 3;
    const int warpM = wid >> 2;
    const int warpN = wid & 3;

    const int nk = K >> 5;

    const uint32_t a_lrow = (uint32_t)(lane & 15) * ROW_PITCH + (uint32_t)(lane >> 4) * 16;
    const uint32_t b_lrow = (uint32_t)((lane & 7) + ((lane >> 4) << 3)) * ROW_PITCH
                          + (uint32_t)((lane >> 3) & 1) * 16;

    auto load_chunk = [&](int c, int s) {
        const uint32_t st = smem_base + (uint32_t)s * STAGE_BYTES;
        const int koff = c * 32;
#pragma unroll
        for (int i = 0; i < 8; i++) {
            int idx  = i * 256 + tid;
            int comp = idx >> 9;            // 0:A 1:(unused) 2:Whi 3:Wlo
            if (comp == 1) continue;
            if (TERMS == 1 && comp == 3) continue;
            int rem  = idx & 511;
            int row  = rem >> 2;
            int seg  = rem & 3;
            uint32_t dst = st + (uint32_t)comp * COMP_BYTES
                         + (uint32_t)row * ROW_PITCH + (uint32_t)seg * 16;
            const unsigned short* src;
            size_t roff;
            if (comp == 0) {
                int gr = m0 + row;
                if (row_idx) gr = __ldg(&row_idx[gr]);
                src = A16;
                roff = (size_t)gr * K;
            } else if (comp == 2) { src = Whi; roff = (size_t)(n0 + row) * K; }
            else                  { src = Wlo; roff = (size_t)(n0 + row) * K; }
            cpasync16(dst, src + roff + koff + seg * 8);
        }
        asm volatile("cp.async.commit_group;" ::: "memory");
    };

    float acc[4][4][4];
#pragma unroll
    for (int i = 0; i < 4; i++)
#pragma unroll
        for (int j = 0; j < 4; j++)
#pragma unroll
            for (int r = 0; r < 4; r++) acc[i][j][r] = 0.f;

    load_chunk(0, 0);

    for (int c = 0; c < nk; c++) {
        if (c + 1 < nk) {
            load_chunk(c + 1, (c + 1) & 1);
            asm volatile("cp.async.wait_group 1;" ::: "memory");
        } else {
            asm volatile("cp.async.wait_group 0;" ::: "memory");
        }
        __syncthreads();

        const uint32_t sb = smem_base + (uint32_t)(c & 1) * STAGE_BYTES;
        const uint32_t aBase = sb + (uint32_t)(warpM * 64) * ROW_PITCH;
        const uint32_t bBase = sb + 2u * COMP_BYTES + (uint32_t)(warpN * 32) * ROW_PITCH;

#pragma unroll
        for (int t = 0; t < 2; t++) {
            const uint32_t kb = (uint32_t)t * 32;

            uint32_t bh[4][2];
#pragma unroll
            for (int jj = 0; jj < 2; jj++) {
                uint32_t r4[4];
                uint32_t addr = bBase + (uint32_t)(jj * 16) * ROW_PITCH + kb + b_lrow;
                ldsm_x4(r4, addr);
                bh[jj * 2][0] = r4[0]; bh[jj * 2][1] = r4[1];
                bh[jj * 2 + 1][0] = r4[2]; bh[jj * 2 + 1][1] = r4[3];
            }
            uint32_t ah[4][4];
#pragma unroll
            for (int i = 0; i < 4; i++)
                ldsm_x4(ah[i], aBase + (uint32_t)(i * 16) * ROW_PITCH + kb + a_lrow);

#pragma unroll
            for (int i = 0; i < 4; i++)
#pragma unroll
                for (int j = 0; j < 4; j++)
                    mma_f16(acc[i][j], ah[i], bh[j]);

            if (TERMS == 2) {
                uint32_t bl[4][2];
#pragma unroll
                for (int jj = 0; jj < 2; jj++) {
                    uint32_t r4[4];
                    uint32_t addr = bBase + COMP_BYTES + (uint32_t)(jj * 16) * ROW_PITCH + kb + b_lrow;
                    ldsm_x4(r4, addr);
                    bl[jj * 2][0] = r4[0]; bl[jj * 2][1] = r4[1];
                    bl[jj * 2 + 1][0] = r4[2]; bl[jj * 2 + 1][1] = r4[3];
                }
#pragma unroll
                for (int i = 0; i < 4; i++)
#pragma unroll
                    for (int j = 0; j < 4; j++)
                        mma_f16(acc[i][j], ah[i], bl[j]);
            }
        }
        __syncthreads();
    }

    // ---- epilogue ----------------------------------------------------------
#pragma unroll
    for (int j = 0; j < 4; j++) {
        const int cc = n0 + warpN * 32 + j * 8 + tk * 2;
        const float b0v = bias[cc];
        const float b1v = bias[cc + 1];
#pragma unroll
        for (int i = 0; i < 4; i++) {
            const int r0 = m0 + warpM * 64 + i * 16 + g;
#pragma unroll
            for (int half = 0; half < 2; half++) {
                const int r = r0 + half * 8;
                float v0 = acc[i][j][half * 2 + 0] + b0v;
                float v1 = acc[i][j][half * 2 + 1] + b1v;
                const size_t off = (size_t)r * Ntot + cc;
                if (OMODE == 2) {
                    *(float2*)(raw_out + off) = make_float2(v0, v1);
                } else {
                    if (write_raw)
                        *(float2*)(raw_out + off) = make_float2(v0, v1);
                    __half h0 = __float2half_rn(fmaxf(v0, 0.f));
                    __half h1 = __float2half_rn(fmaxf(v1, 0.f));
                    uint32_t hp = (uint32_t)__half_as_ushort(h0)
                                | ((uint32_t)__half_as_ushort(h1) << 16);
                    *(uint32_t*)(O16 + off) = hp;
                }
            }
        }
    }
}

// ---- prep: relu(x) -> fp16 --------------------------------------------------
__global__ void prep_x(const float* __restrict__ src,
                       unsigned short* __restrict__ o, int n)
{
    int t = blockIdx.x * blockDim.x + threadIdx.x;
    if (t >= n) return;
    o[t] = __half_as_ushort(__float2half_rn(fmaxf(src[t], 0.0f)));
}

// ---- prep: ALL weights transpose (+split for trunk) -------------------------
__global__ void prep_all(const float* __restrict__ W0, const float* __restrict__ W1,
                         const float* __restrict__ W2, const float* __restrict__ SW0,
                         const float* __restrict__ SW1,
                         unsigned short* __restrict__ hi, unsigned short* __restrict__ lo)
{
    int t = blockIdx.x * blockDim.x + threadIdx.x;
    if (t >= 1736704) return;
    const float* src;
    int local, Kd, Nd;
    unsigned int dbase;
    bool trunk = false;
    if (t < 294912) {
        trunk = true;
        if (t < 32768) { src = W0; local = t; Kd = 64; Nd = 512; dbase = OFF_W0; }
        else           { src = W1; local = t - 32768; Kd = 512; Nd = 512; dbase = OFF_W1; }
    } else if (t < 557056) {
        trunk = true;
        src = W2; local = t - 294912; Kd = 512; Nd = 512; dbase = OFF_W2;
    } else if (t < 1343488) {
        int u = t - 557056;
        int p = u / 262144;
        local = u - p * 262144;
        src = SW0 + (size_t)p * 262144; Kd = 512; Nd = 512;
        dbase = OFF_SW0 + (unsigned int)p * 262144u;
    } else {
        int u = t - 1343488;
        int p = u / 131072;
        local = u - p * 131072;
        src = SW1 + (size_t)p * 131072; Kd = 512; Nd = 256;
        dbase = OFF_SW1 + (unsigned int)p * 131072u;
    }
    int k = local / Nd, n = local % Nd;
    float v = src[local];
    size_t d = (size_t)dbase + (size_t)n * Kd + k;
    if (trunk) {
        __half h, l;
        split_fp16(v, h, l);
        hi[d] = __half_as_ushort(h);
        lo[d] = __half_as_ushort(l);
    } else {
        hi[d] = __half_as_ushort(__float2half_rn(v));
    }
}

// ---- index build ------------------------------------------------------------
__global__ void idx_reset() {
    if (threadIdx.x < 4) { g_cnt[threadIdx.x] = 0; g_cntpad[threadIdx.x] = 0; }
}
__global__ void idx_build(const int* __restrict__ y, const int* __restrict__ pairs, int n)
{
    int t = blockIdx.x * blockDim.x + threadIdx.x;
    if (t >= n) return;
    int yv = y[t];
#pragma unroll
    for (int p = 0; p < 3; p++) {
        if (yv == pairs[2 * p] || yv == pairs[2 * p + 1]) {
            int pos = atomicAdd(&g_cnt[p], 1);
            g_idx[p * IDX_STRIDE + pos] = t;
        }
    }
}
__global__ void idx_pad()
{
    int p = blockIdx.x;
    int c = g_cnt[p];
    int cp = (c + 127) & ~127;
    for (int i = c + threadIdx.x; i < cp; i += 128)
        g_idx[p * IDX_STRIDE + i] = 0;
    if (threadIdx.x == 0) g_cntpad[p] = cp;
}

// ---- final (z-batched): fp32 packed rows, scatter to original index ---------
__global__ void subnet_final(const float* __restrict__ fC_base,
                             const float* __restrict__ SW2,
                             const float* __restrict__ Sb2,
                             const int*   __restrict__ idx_base,
                             const int*   __restrict__ cnt_base,
                             float* __restrict__ out_r,
                             float* __restrict__ out_s,
                             float* __restrict__ out_m)
{
    const int p = blockIdx.z;
    const float* fC = fC_base + (size_t)p * GN * 256;
    const int* idxlist = idx_base + (size_t)p * IDX_STRIDE;
    float* r_out = out_r + (size_t)p * GN;
    float* s_out = out_s + (size_t)p * GN;
    float* m_out = out_m + (size_t)p * GN;

    __shared__ float w[256];
    const int tid = threadIdx.x;
    w[tid] = SW2[p * 256 + tid];
    __syncthreads();

    const float sb = Sb2[p];
    const int limit = __ldg(cnt_base + p);

    const int lane = tid & 31;
    const int warp = tid >> 5;
    const int gw = blockIdx.x * (blockDim.x >> 5) + warp;
    const int warps_total = gridDim.x * (blockDim.x >> 5);

    for (int n = gw; n < limit; n += warps_total) {
        const size_t base = (size_t)n * 256;
        float acc = 0.f;
#pragma unroll
        for (int j = 0; j < 8; j++) {
            int c = lane + 32 * j;
            acc += fmaxf(fC[base + c], 0.f) * w[c];
        }
#pragma unroll
        for (int o = 16; o > 0; o >>= 1)
            acc += __shfl_xor_sync(0xFFFFFFFFu, acc, o);

        if (lane == 0) {
            float logit = acc + sb;
            float s = 1.f / (1.f + expf(-logit));
            s = fmaxf(s, 1e-9f);
            float r = (1.f - s) / s;
            int orig = __ldg(&idxlist[n]);
            r_out[orig] = r;
            s_out[orig] = s;
            m_out[orig] = 1.f;
        }
    }
}

// ============================================================================
extern "C" void kernel_launch(void* const* d_in, const int* in_sizes, int n_in,
                              void* d_out, int out_size)
{
    const float* x     = (const float*)d_in[0];
    const int*   y     = (const int*)  d_in[1];
    const int*   pairs = (const int*)  d_in[2];
    const float* W0    = (const float*)d_in[3];
    const float* b0    = (const float*)d_in[4];
    const float* W1    = (const float*)d_in[5];
    const float* b1    = (const float*)d_in[6];
    const float* W2    = (const float*)d_in[7];
    const float* b2    = (const float*)d_in[8];
    const float* SW0   = (const float*)d_in[9];
    const float* Sb0   = (const float*)d_in[10];
    const float* SW1   = (const float*)d_in[11];
    const float* Sb1   = (const float*)d_in[12];
    const float* SW2   = (const float*)d_in[13];
    const float* Sb2   = (const float*)d_in[14];

    const int M = GN;
    float* out   = (float*)d_out;
    float* repr  = out;
    float* r_seg = out + (size_t)M * 512;
    float* s_seg = r_seg + 3 * (size_t)M;
    float* m_seg = s_seg + 3 * (size_t)M;

    unsigned short *X16, *A, *B, *whi, *wlo;
    float *fC;
    cudaGetSymbolAddress((void**)&X16, g_X16);
    cudaGetSymbolAddress((void**)&A,   g_A);
    cudaGetSymbolAddress((void**)&B,   g_B);
    cudaGetSymbolAddress((void**)&fC,  g_fC);
    cudaGetSymbolAddress((void**)&whi, g_whi);
    cudaGetSymbolAddress((void**)&wlo, g_wlo);
    int *idxp, *cntp, *cntpadp;
    cudaGetSymbolAddress((void**)&idxp, g_idx);
    cudaGetSymbolAddress((void**)&cntp, g_cnt);
    cudaGetSymbolAddress((void**)&cntpadp, g_cntpad);

    cudaFuncSetAttribute((const void*)gemm_mma<2,1>,
        cudaFuncAttributeMaxDynamicSharedMemorySize, 2 * STAGE_BYTES);
    cudaFuncSetAttribute((const void*)gemm_mma<1,1>,
        cudaFuncAttributeMaxDynamicSharedMemorySize, 2 * STAGE_BYTES);
    cudaFuncSetAttribute((const void*)gemm_mma<1,2>,
        cudaFuncAttributeMaxDynamicSharedMemorySize, 2 * STAGE_BYTES);

    cudaMemsetAsync(r_seg, 0, 9 * (size_t)M * sizeof(float));

    prep_x<<<(M * 64 + 255) / 256, 256>>>(x, X16, M * 64);
    prep_all<<<(1736704 + 255) / 256, 256>>>(W0, W1, W2, SW0, SW1, whi, wlo);
    idx_reset<<<1, 32>>>();
    idx_build<<<(M + 255) / 256, 256>>>(y, pairs, M);
    idx_pad<<<3, 128>>>();

    dim3 blk(256);
    const size_t shmem = 2 * STAGE_BYTES;

    // trunk: 2-term fp16, fp16 activations
    gemm_mma<2,1><<<dim3(4, M / 128, 1), blk, shmem>>>(
        X16, 0, whi + OFF_W0, wlo + OFF_W0, 0, b0, 0,
        nullptr, 0, A, 0, 64, 512, 0, nullptr, nullptr);
    gemm_mma<2,1><<<dim3(4, M / 128, 1), blk, shmem>>>(
        A, 0, whi + OFF_W1, wlo + OFF_W1, 0, b1, 0,
        nullptr, 0, B, 0, 512, 512, 0, nullptr, nullptr);
    gemm_mma<2,1><<<dim3(4, M / 128, 1), blk, shmem>>>(
        B, 0, whi + OFF_W2, wlo + OFF_W2, 0, b2, 0,
        repr, 0, A, 0, 512, 512, 1, nullptr, nullptr);

    // SW0: 1-term fp16, z-batched, gathered rows
    gemm_mma<1,1><<<dim3(4, M / 128, 3), blk, shmem>>>(
        A, 0, whi + OFF_SW0, whi + OFF_SW0, 262144, Sb0, 512,
        nullptr, 0, B, (size_t)GN * 512,
        512, 512, 0, idxp, cntpadp);

    // SW1: 1-term fp16, z-batched, fp32 raw outputs
    gemm_mma<1,2><<<dim3(2, M / 128, 3), blk, shmem>>>(
        B, (size_t)GN * 512, whi + OFF_SW1, whi + OFF_SW1, 131072, Sb1, 256,
        fC, (size_t)GN * 256, nullptr, 0,
        512, 256, 0, nullptr, cntpadp);

    // final
    subnet_final<<<dim3(512, 1, 3), dim3(256)>>>(
        fC, SW2, Sb2, idxp, cntp, r_seg, s_seg, m_seg);
}

// round 14
// speedup vs baseline: 3.1067x; 1.0965x over previous
#include <cuda_runtime.h>
#include <cuda_bf16.h>
#include <cuda_fp16.h>
#include <cstdint>
#include <math.h>

// ============================================================================
// EnsembleRatioModel — round 13: identical to round 12 (infra failure, resubmit).
// K-chunk 64 + profiling-friendly launch order. Precision frozen at R11:
//   Trunk:  2-term fp16 (A . (Whi+Wlo));  Subnet: 1-term fp16 (A . W)
// Row compaction + z-batched subnet launches retained.
//
// Output packing (validated): [N*512) repr_ ; [3N) r*m ; [3N) s*m ; [3N) m
// ============================================================================

#define GN 131072

__device__ unsigned short g_X16[GN * 64];             // fp16 relu(x)
__device__ unsigned short g_A[GN * 512];              // fp16 trunk act ping
__device__ unsigned short g_B[3ULL * GN * 512];       // trunk pong (slice 0) + SW0 outs
__device__ float          g_fC[3ULL * GN * 256];      // SW1 raw fp32 outs
__device__ unsigned short g_whi[1736704];             // all weights, fp16 hi
__device__ unsigned short g_wlo[557056];              // trunk weights fp16 lo only

__device__ int g_cnt[4];
__device__ int g_cntpad[4];
__device__ int g_idx[3 * (GN + 128)];

#define IDX_STRIDE (GN + 128)

#define OFF_W0   0u
#define OFF_W1   32768u
#define OFF_W2   294912u
#define OFF_SW0  557056u      /* + p*262144 */
#define OFF_SW1  1343488u     /* + p*131072 */

// ---------------- helpers ----------------------------------------------------
__device__ __forceinline__ uint32_t smem_u32(const void* p) {
    uint32_t a;
    asm("{ .reg .u64 t; cvta.to.shared.u64 t, %1; cvt.u32.u64 %0, t; }"
        : "=r"(a) : "l"(p));
    return a;
}
__device__ __forceinline__ void cpasync16(uint32_t dst, const void* src) {
    asm volatile("cp.async.cg.shared.global [%0], [%1], 16;"
                 :: "r"(dst), "l"(src) : "memory");
}
__device__ __forceinline__ void ldsm_x4(uint32_t* r, uint32_t addr) {
    asm volatile("ldmatrix.sync.aligned.m8n8.x4.shared.b16 {%0,%1,%2,%3}, [%4];"
                 : "=r"(r[0]), "=r"(r[1]), "=r"(r[2]), "=r"(r[3]) : "r"(addr));
}
__device__ __forceinline__ void mma_f16(float* d, const uint32_t* a,
                                        const uint32_t* b) {
    asm volatile(
        "mma.sync.aligned.m16n8k16.row.col.f32.f16.f16.f32 "
        "{%0,%1,%2,%3}, {%4,%5,%6,%7}, {%8,%9}, {%0,%1,%2,%3};"
        : "+f"(d[0]), "+f"(d[1]), "+f"(d[2]), "+f"(d[3])
        : "r"(a[0]), "r"(a[1]), "r"(a[2]), "r"(a[3]), "r"(b[0]), "r"(b[1]));
}
__device__ __forceinline__ void split_fp16(float v, __half& h, __half& l) {
    h = __float2half_rn(v);
    l = __float2half_rn(v - __half2float(h));
}

// ============================================================================
// GEMM template. TERMS: 2 = A.(Whi+Wlo), 1 = A.Whi.
// OMODE: 1 = fp16 single out (+opt fp32 raw); 2 = fp32 raw out only.
// 128x128 CTA tile, 256 thr, warp 64x32, K-chunk 64, double buffer.
// SMEM per stage: comps {A, Whi[, Wlo]} x 128 rows x 144B pitch (128B data).
// ============================================================================
#define ROW_PITCH  144
#define COMP_BYTES 18432      /* 128 * 144 */

template<int TERMS, int OMODE>
__global__ void __launch_bounds__(256, 2)
gemm_mma(const unsigned short* __restrict__ A16, size_t a_ps,
         const unsigned short* __restrict__ Whi, const unsigned short* __restrict__ Wlo,
         size_t w_ps,
         const float* __restrict__ bias, size_t b_ps,
         float* __restrict__ raw_out, size_t r_ps,
         unsigned short* __restrict__ O16, size_t o_ps,
         int K, int Ntot, int write_raw,
         const int* __restrict__ row_idx_base, const int* __restrict__ cnt_base)
{
    constexpr uint32_t STAGE = (TERMS + 1) * COMP_BYTES;
    extern __shared__ __align__(16) char smem[];
    const uint32_t smem_base = smem_u32(smem);

    const int p  = blockIdx.z;
    const int m0 = blockIdx.y * 128;
    if (cnt_base && m0 >= __ldg(cnt_base + p)) return;
    const int n0 = blockIdx.x * 128;

    const int* row_idx = row_idx_base ? row_idx_base + (size_t)p * IDX_STRIDE : nullptr;
    A16 += (size_t)p * a_ps;
    Whi += (size_t)p * w_ps;
    Wlo += (size_t)p * w_ps;
    bias += (size_t)p * b_ps;
    raw_out += (size_t)p * r_ps;
    O16 += (size_t)p * o_ps;

    const int tid   = threadIdx.x;
    const int wid   = tid >> 5;
    const int lane  = tid & 31;
    const int g     = lane >> 2;
    const int tk    = lane & 3;
    const int warpM = wid >> 2;
    const int warpN = wid & 3;

    const int nk = K >> 6;     // K-chunks of 64

    const uint32_t a_lrow = (uint32_t)(lane & 15) * ROW_PITCH + (uint32_t)(lane >> 4) * 16;
    const uint32_t b_lrow = (uint32_t)((lane & 7) + ((lane >> 4) << 3)) * ROW_PITCH
                          + (uint32_t)((lane >> 3) & 1) * 16;

    auto load_chunk = [&](int c, int s) {
        const uint32_t st = smem_base + (uint32_t)s * STAGE;
        const int koff = c * 64;
        constexpr int NITER = (TERMS == 2) ? 12 : 8;
#pragma unroll
        for (int i = 0; i < NITER; i++) {
            int idx  = i * 256 + tid;
            int comp = idx >> 10;           // 0:A 1:Whi 2:Wlo
            int rem  = idx & 1023;
            int row  = rem >> 3;
            int seg  = rem & 7;
            uint32_t dst = st + (uint32_t)comp * COMP_BYTES
                         + (uint32_t)row * ROW_PITCH + (uint32_t)seg * 16;
            const unsigned short* src;
            size_t roff;
            if (comp == 0) {
                int gr = m0 + row;
                if (row_idx) gr = __ldg(&row_idx[gr]);
                src = A16;
                roff = (size_t)gr * K;
            } else if (comp == 1) { src = Whi; roff = (size_t)(n0 + row) * K; }
            else                  { src = Wlo; roff = (size_t)(n0 + row) * K; }
            cpasync16(dst, src + roff + koff + seg * 8);
        }
        asm volatile("cp.async.commit_group;" ::: "memory");
    };

    float acc[4][4][4];
#pragma unroll
    for (int i = 0; i < 4; i++)
#pragma unroll
        for (int j = 0; j < 4; j++)
#pragma unroll
            for (int r = 0; r < 4; r++) acc[i][j][r] = 0.f;

    load_chunk(0, 0);

    for (int c = 0; c < nk; c++) {
        if (c + 1 < nk) {
            load_chunk(c + 1, (c + 1) & 1);
            asm volatile("cp.async.wait_group 1;" ::: "memory");
        } else {
            asm volatile("cp.async.wait_group 0;" ::: "memory");
        }
        __syncthreads();

        const uint32_t sb = smem_base + (uint32_t)(c & 1) * STAGE;
        const uint32_t aBase = sb + (uint32_t)(warpM * 64) * ROW_PITCH;
        const uint32_t bBase = sb + COMP_BYTES + (uint32_t)(warpN * 32) * ROW_PITCH;

#pragma unroll
        for (int t = 0; t < 4; t++) {
            const uint32_t kb = (uint32_t)t * 32;

            uint32_t bh[4][2];
#pragma unroll
            for (int jj = 0; jj < 2; jj++) {
                uint32_t r4[4];
                uint32_t addr = bBase + (uint32_t)(jj * 16) * ROW_PITCH + kb + b_lrow;
                ldsm_x4(r4, addr);
                bh[jj * 2][0] = r4[0]; bh[jj * 2][1] = r4[1];
                bh[jj * 2 + 1][0] = r4[2]; bh[jj * 2 + 1][1] = r4[3];
            }
            uint32_t ah[4][4];
#pragma unroll
            for (int i = 0; i < 4; i++)
                ldsm_x4(ah[i], aBase + (uint32_t)(i * 16) * ROW_PITCH + kb + a_lrow);

#pragma unroll
            for (int i = 0; i < 4; i++)
#pragma unroll
                for (int j = 0; j < 4; j++)
                    mma_f16(acc[i][j], ah[i], bh[j]);

            if (TERMS == 2) {
                uint32_t bl[4][2];
#pragma unroll
                for (int jj = 0; jj < 2; jj++) {
                    uint32_t r4[4];
                    uint32_t addr = bBase + COMP_BYTES + (uint32_t)(jj * 16) * ROW_PITCH + kb + b_lrow;
                    ldsm_x4(r4, addr);
                    bl[jj * 2][0] = r4[0]; bl[jj * 2][1] = r4[1];
                    bl[jj * 2 + 1][0] = r4[2]; bl[jj * 2 + 1][1] = r4[3];
                }
#pragma unroll
                for (int i = 0; i < 4; i++)
#pragma unroll
                    for (int j = 0; j < 4; j++)
                        mma_f16(acc[i][j], ah[i], bl[j]);
            }
        }
        __syncthreads();
    }

    // ---- epilogue ----------------------------------------------------------
#pragma unroll
    for (int j = 0; j < 4; j++) {
        const int cc = n0 + warpN * 32 + j * 8 + tk * 2;
        const float b0v = bias[cc];
        const float b1v = bias[cc + 1];
#pragma unroll
        for (int i = 0; i < 4; i++) {
            const int r0 = m0 + warpM * 64 + i * 16 + g;
#pragma unroll
            for (int half = 0; half < 2; half++) {
                const int r = r0 + half * 8;
                float v0 = acc[i][j][half * 2 + 0] + b0v;
                float v1 = acc[i][j][half * 2 + 1] + b1v;
                const size_t off = (size_t)r * Ntot + cc;
                if (OMODE == 2) {
                    *(float2*)(raw_out + off) = make_float2(v0, v1);
                } else {
                    if (write_raw)
                        *(float2*)(raw_out + off) = make_float2(v0, v1);
                    __half h0 = __float2half_rn(fmaxf(v0, 0.f));
                    __half h1 = __float2half_rn(fmaxf(v1, 0.f));
                    uint32_t hp = (uint32_t)__half_as_ushort(h0)
                                | ((uint32_t)__half_as_ushort(h1) << 16);
                    *(uint32_t*)(O16 + off) = hp;
                }
            }
        }
    }
}

// ---- prep: relu(x) -> fp16 --------------------------------------------------
__global__ void prep_x(const float* __restrict__ src,
                       unsigned short* __restrict__ o, int n)
{
    int t = blockIdx.x * blockDim.x + threadIdx.x;
    if (t >= n) return;
    o[t] = __half_as_ushort(__float2half_rn(fmaxf(src[t], 0.0f)));
}

// ---- prep: ALL weights transpose (+split for trunk) -------------------------
__global__ void prep_all(const float* __restrict__ W0, const float* __restrict__ W1,
                         const float* __restrict__ W2, const float* __restrict__ SW0,
                         const float* __restrict__ SW1,
                         unsigned short* __restrict__ hi, unsigned short* __restrict__ lo)
{
    int t = blockIdx.x * blockDim.x + threadIdx.x;
    if (t >= 1736704) return;
    const float* src;
    int local, Kd, Nd;
    unsigned int dbase;
    bool trunk = false;
    if (t < 294912) {
        trunk = true;
        if (t < 32768) { src = W0; local = t; Kd = 64; Nd = 512; dbase = OFF_W0; }
        else           { src = W1; local = t - 32768; Kd = 512; Nd = 512; dbase = OFF_W1; }
    } else if (t < 557056) {
        trunk = true;
        src = W2; local = t - 294912; Kd = 512; Nd = 512; dbase = OFF_W2;
    } else if (t < 1343488) {
        int u = t - 557056;
        int p = u / 262144;
        local = u - p * 262144;
        src = SW0 + (size_t)p * 262144; Kd = 512; Nd = 512;
        dbase = OFF_SW0 + (unsigned int)p * 262144u;
    } else {
        int u = t - 1343488;
        int p = u / 131072;
        local = u - p * 131072;
        src = SW1 + (size_t)p * 131072; Kd = 512; Nd = 256;
        dbase = OFF_SW1 + (unsigned int)p * 131072u;
    }
    int k = local / Nd, n = local % Nd;
    float v = src[local];
    size_t d = (size_t)dbase + (size_t)n * Kd + k;
    if (trunk) {
        __half h, l;
        split_fp16(v, h, l);
        hi[d] = __half_as_ushort(h);
        lo[d] = __half_as_ushort(l);
    } else {
        hi[d] = __half_as_ushort(__float2half_rn(v));
    }
}

// ---- index build (g_cnt zeroed via cudaMemsetAsync host-side) ---------------
__global__ void idx_build(const int* __restrict__ y, const int* __restrict__ pairs, int n)
{
    int t = blockIdx.x * blockDim.x + threadIdx.x;
    if (t >= n) return;
    int yv = y[t];
#pragma unroll
    for (int p = 0; p < 3; p++) {
        if (yv == pairs[2 * p] || yv == pairs[2 * p + 1]) {
            int pos = atomicAdd(&g_cnt[p], 1);
            g_idx[p * IDX_STRIDE + pos] = t;
        }
    }
}
__global__ void idx_pad()
{
    int p = blockIdx.x;
    int c = g_cnt[p];
    int cp = (c + 127) & ~127;
    for (int i = c + threadIdx.x; i < cp; i += 128)
        g_idx[p * IDX_STRIDE + i] = 0;
    if (threadIdx.x == 0) g_cntpad[p] = cp;
}

// ---- final (z-batched): fp32 packed rows, scatter to original index ---------
__global__ void subnet_final(const float* __restrict__ fC_base,
                             const float* __restrict__ SW2,
                             const float* __restrict__ Sb2,
                             const int*   __restrict__ idx_base,
                             const int*   __restrict__ cnt_base,
                             float* __restrict__ out_r,
                             float* __restrict__ out_s,
                             float* __restrict__ out_m)
{
    const int p = blockIdx.z;
    const float* fC = fC_base + (size_t)p * GN * 256;
    const int* idxlist = idx_base + (size_t)p * IDX_STRIDE;
    float* r_out = out_r + (size_t)p * GN;
    float* s_out = out_s + (size_t)p * GN;
    float* m_out = out_m + (size_t)p * GN;

    __shared__ float w[256];
    const int tid = threadIdx.x;
    w[tid] = SW2[p * 256 + tid];
    __syncthreads();

    const float sb = Sb2[p];
    const int limit = __ldg(cnt_base + p);

    const int lane = tid & 31;
    const int warp = tid >> 5;
    const int gw = blockIdx.x * (blockDim.x >> 5) + warp;
    const int warps_total = gridDim.x * (blockDim.x >> 5);

    for (int n = gw; n < limit; n += warps_total) {
        const size_t base = (size_t)n * 256;
        float acc = 0.f;
#pragma unroll
        for (int j = 0; j < 8; j++) {
            int c = lane + 32 * j;
            acc += fmaxf(fC[base + c], 0.f) * w[c];
        }
#pragma unroll
        for (int o = 16; o > 0; o >>= 1)
            acc += __shfl_xor_sync(0xFFFFFFFFu, acc, o);

        if (lane == 0) {
            float logit = acc + sb;
            float s = 1.f / (1.f + expf(-logit));
            s = fmaxf(s, 1e-9f);
            float r = (1.f - s) / s;
            int orig = __ldg(&idxlist[n]);
            r_out[orig] = r;
            s_out[orig] = s;
            m_out[orig] = 1.f;
        }
    }
}

// ============================================================================
extern "C" void kernel_launch(void* const* d_in, const int* in_sizes, int n_in,
                              void* d_out, int out_size)
{
    const float* x     = (const float*)d_in[0];
    const int*   y     = (const int*)  d_in[1];
    const int*   pairs = (const int*)  d_in[2];
    const float* W0    = (const float*)d_in[3];
    const float* b0    = (const float*)d_in[4];
    const float* W1    = (const float*)d_in[5];
    const float* b1    = (const float*)d_in[6];
    const float* W2    = (const float*)d_in[7];
    const float* b2    = (const float*)d_in[8];
    const float* SW0   = (const float*)d_in[9];
    const float* Sb0   = (const float*)d_in[10];
    const float* SW1   = (const float*)d_in[11];
    const float* Sb1   = (const float*)d_in[12];
    const float* SW2   = (const float*)d_in[13];
    const float* Sb2   = (const float*)d_in[14];

    const int M = GN;
    float* out   = (float*)d_out;
    float* repr  = out;
    float* r_seg = out + (size_t)M * 512;
    float* s_seg = r_seg + 3 * (size_t)M;
    float* m_seg = s_seg + 3 * (size_t)M;

    unsigned short *X16, *A, *B, *whi, *wlo;
    float *fC;
    cudaGetSymbolAddress((void**)&X16, g_X16);
    cudaGetSymbolAddress((void**)&A,   g_A);
    cudaGetSymbolAddress((void**)&B,   g_B);
    cudaGetSymbolAddress((void**)&fC,  g_fC);
    cudaGetSymbolAddress((void**)&whi, g_whi);
    cudaGetSymbolAddress((void**)&wlo, g_wlo);
    int *idxp, *cntp, *cntpadp;
    cudaGetSymbolAddress((void**)&idxp, g_idx);
    cudaGetSymbolAddress((void**)&cntp, g_cnt);
    cudaGetSymbolAddress((void**)&cntpadp, g_cntpad);

    cudaFuncSetAttribute((const void*)gemm_mma<2,1>,
        cudaFuncAttributeMaxDynamicSharedMemorySize, 2 * 3 * COMP_BYTES);
    cudaFuncSetAttribute((const void*)gemm_mma<1,1>,
        cudaFuncAttributeMaxDynamicSharedMemorySize, 2 * 2 * COMP_BYTES);
    cudaFuncSetAttribute((const void*)gemm_mma<1,2>,
        cudaFuncAttributeMaxDynamicSharedMemorySize, 2 * 2 * COMP_BYTES);

    // memsets are graph memset nodes, not kernels — keeps GEMM at kernel #6
    cudaMemsetAsync(r_seg, 0, 9 * (size_t)M * sizeof(float));
    cudaMemsetAsync(cntp, 0, 4 * sizeof(int));

    prep_x<<<(M * 64 + 255) / 256, 256>>>(x, X16, M * 64);          // k1
    prep_all<<<(1736704 + 255) / 256, 256>>>(W0, W1, W2, SW0, SW1, whi, wlo); // k2
    idx_build<<<(M + 255) / 256, 256>>>(y, pairs, M);               // k3
    idx_pad<<<3, 128>>>();                                          // k4

    dim3 blk(256);
    const size_t sh2 = 2 * 3 * COMP_BYTES;   // 110592
    const size_t sh1 = 2 * 2 * COMP_BYTES;   // 73728

    // trunk: 2-term fp16                                            k5, k6, k7
    gemm_mma<2,1><<<dim3(4, M / 128, 1), blk, sh2>>>(
        X16, 0, whi + OFF_W0, wlo + OFF_W0, 0, b0, 0,
        nullptr, 0, A, 0, 64, 512, 0, nullptr, nullptr);
    gemm_mma<2,1><<<dim3(4, M / 128, 1), blk, sh2>>>(
        A, 0, whi + OFF_W1, wlo + OFF_W1, 0, b1, 0,
        nullptr, 0, B, 0, 512, 512, 0, nullptr, nullptr);
    gemm_mma<2,1><<<dim3(4, M / 128, 1), blk, sh2>>>(
        B, 0, whi + OFF_W2, wlo + OFF_W2, 0, b2, 0,
        repr, 0, A, 0, 512, 512, 1, nullptr, nullptr);

    // SW0: 1-term fp16, z-batched, gathered rows
    gemm_mma<1,1><<<dim3(4, M / 128, 3), blk, sh1>>>(
        A, 0, whi + OFF_SW0, whi + OFF_SW0, 262144, Sb0, 512,
        nullptr, 0, B, (size_t)GN * 512,
        512, 512, 0, idxp, cntpadp);

    // SW1: 1-term fp16, z-batched, fp32 raw outputs
    gemm_mma<1,2><<<dim3(2, M / 128, 3), blk, sh1>>>(
        B, (size_t)GN * 512, whi + OFF_SW1, whi + OFF_SW1, 131072, Sb1, 256,
        fC, (size_t)GN * 256, nullptr, 0,
        512, 256, 0, nullptr, cntpadp);

    // final
    subnet_final<<<dim3(512, 1, 3), dim3(256)>>>(
        fC, SW2, Sb2, idxp, cntp, r_seg, s_seg, m_seg);
}